// round 14
// baseline (speedup 1.0000x reference)
#include <cuda_runtime.h>

#define B_    4
#define NH_   4
#define N_    1000
#define NF_   256
#define K_TOP 10
#define NODES (B_*N_)       // 4000
#define EDGES (B_*K_TOP*N_) // 40000

// ---- scratch layout (floats) ----
#define OFF_SCUR 0
#define OFF_ACUR (OFF_SCUR + NODES*3)
#define OFF_PEIN (OFF_ACUR + NODES)
#define OFF_FLAG (OFF_PEIN + NODES*16)
#define OFF_REIN (OFF_FLAG + EDGES)
#define OFF_BUFA (OFF_REIN + EDGES*5)
#define OFF_BUFB (OFF_BUFA + EDGES*NF_)
#define OFF_BASE (OFF_BUFB + EDGES*NF_)
#define OFF_PEH  (OFF_BASE + EDGES*NF_)
#define OFF_PE   (OFF_PEH  + NODES*NF_)
#define OFF_G23  (OFF_PE   + NODES*NF_)          // NODES x 512
#define OFF_AGG  (OFF_G23  + NODES*2*NF_)
#define OFF_PPC  (OFF_AGG  + NODES*NF_)
#define OFF_WPE1 (OFF_PPC  + NODES*NF_)
#define OFF_WRE1 (OFF_WPE1 + NF_*NF_)
#define OFF_WRE2 (OFF_WRE1 + NF_*NF_)
#define OFF_WRP  (OFF_WRE2 + NF_*NF_)            // 768x256 (only [0:256] used for base)
#define OFF_WPP  (OFF_WRP  + 3*NF_*NF_)
#define OFF_WPR0 (OFF_WPP  + 2*NF_*NF_)
#define OFF_WG23 (OFF_WPR0 + NF_*NF_)            // 256x512 column-concat [W2|W3]
#define SCRATCH_TOTAL (OFF_WG23 + NF_*2*NF_)

__device__ float g_scratch[SCRATCH_TOTAL];
__device__ int   g_send[EDGES];
__device__ int   g_sendc[EDGES];
__device__ int   g_offsets[NODES+1];
__device__ int   g_Mact[1];

__device__ __forceinline__ float f2tff(float x) {
    unsigned r;
    asm("cvt.rna.tf32.f32 %0, %1;" : "=r"(r) : "f"(x));
    return __uint_as_float(r);
}

// ---------------------------------------------------------------------------
// combo: topk (8-way split) + prep + wcvt (incl. wG23 concat) — one launch
// ---------------------------------------------------------------------------
#define COMBO_TOPK   128
#define COMBO_PREP   16
#define COMBO_WCVT   (2304 + 512)
#define COMBO_BLOCKS (COMBO_TOPK + COMBO_PREP + COMBO_WCVT)

__global__ void __launch_bounds__(256)
combo_kernel(const float* __restrict__ a_hist,
             const float* __restrict__ s_hist,
             const float* __restrict__ s_delta,
             const float* __restrict__ pr_b1,
             const float* __restrict__ pe_w1, const float* __restrict__ re_w1,
             const float* __restrict__ re_w2, const float* __restrict__ rp_w,
             const float* __restrict__ pp_w,  const float* __restrict__ pr_w0,
             float* __restrict__ S,
             int* __restrict__ send, float* __restrict__ flag,
             float* __restrict__ out)
{
    int bid = blockIdx.x;
    int tid = threadIdx.x;

    if (bid < COMBO_TOPK) {
        __shared__ float sx[N_], sy[N_], sz[N_];
        __shared__ unsigned char st[N_];
        __shared__ float md[256][K_TOP];
        __shared__ short mi[256][K_TOP];
        int b = bid >> 5;
        int xb = bid & 31;
        for (int j = tid; j < N_; j += 256) {
            const float* sh = s_hist + ((size_t)(b*NH_ + NH_-1)*N_ + j)*3;
            sx[j]=sh[0]; sy[j]=sh[1]; sz[j]=sh[2];
            st[j] = a_hist[(b*NH_ + NH_-1)*N_ + j] > 0.5f ? 1 : 0;
        }
        __syncthreads();
        int li = tid & 31;
        int part = tid >> 5;
        int i = xb*32 + li;
        float dv[K_TOP]; short iv[K_TOP];
#pragma unroll
        for (int t=0;t<K_TOP;++t){ dv[t]=3.0e38f; iv[t]=0; }
        if (i < N_) {
            bool ti = st[i] != 0;
            float xi=sx[i], yi=sy[i], zi=sz[i];
            int j0 = part*125, j1 = j0+125;
            for (int j=j0;j<j1;++j) {
                float dx=__fadd_rn(xi,-sx[j]), dy=__fadd_rn(yi,-sy[j]), dz=__fadd_rn(zi,-sz[j]);
                float d = __fadd_rn(__fadd_rn(__fmul_rn(dx,dx),__fmul_rn(dy,dy)),__fmul_rn(dz,dz));
                if (ti && st[j]) d = 1e10f;
                if (d < dv[K_TOP-1]) {
#pragma unroll
                    for (int t=K_TOP-1; t>=1; --t) {
                        if (d < dv[t-1])      { dv[t]=dv[t-1]; iv[t]=iv[t-1]; }
                        else if (d < dv[t])   { dv[t]=d;       iv[t]=(short)j; }
                    }
                    if (d < dv[0]) { dv[0]=d; iv[0]=(short)j; }
                }
            }
        }
#pragma unroll
        for (int t=0;t<K_TOP;++t){ md[tid][t]=dv[t]; mi[tid][t]=iv[t]; }
        __syncthreads();
        if (part == 0 && i < N_) {
            bool ti = st[i] != 0;
            int ptr[8] = {0,0,0,0,0,0,0,0};
            int gi = b*N_ + i;
#pragma unroll
            for (int t=0;t<K_TOP;++t) {
                float best = 3.5e38f; int bp = 0;
#pragma unroll
                for (int p=0;p<8;++p) {
                    float dd = md[li + p*32][ptr[p]];
                    if (dd < best) { best = dd; bp = p; }
                }
                int j = mi[li + bp*32][ptr[bp]];
                ptr[bp]++;
                int rg = gi*K_TOP + t;
                send[rg] = b*N_ + j;
                flag[rg] = (!ti && best < 0.25f) ? 1.0f : 0.0f;
            }
        }
    } else if (bid < COMBO_TOPK + COMBO_PREP) {
        int idx = (bid - COMBO_TOPK)*256 + tid;
        if (idx >= NODES) return;
        int b = idx / N_, n = idx % N_;
        float* scur = S + OFF_SCUR;
        float* acur = S + OFF_ACUR;
        float* pein = S + OFF_PEIN;
        acur[idx] = a_hist[(b*NH_ + NH_-1)*N_ + n];
        const float* sh = s_hist + ((size_t)(b*NH_ + NH_-1)*N_ + n)*3;
        float s0=sh[0], s1=sh[1], s2=sh[2];
        scur[idx*3+0]=s0; scur[idx*3+1]=s1; scur[idx*3+2]=s2;
        out[idx*3+0] = s0 + pr_b1[0];
        out[idx*3+1] = s1 + pr_b1[1];
        out[idx*3+2] = s2 + pr_b1[2];
        float* pp = pein + (size_t)idx*16;
#pragma unroll
        for (int h=0; h<NH_; ++h) {
            const float* sd = s_delta + ((size_t)(b*NH_+h)*N_ + n)*3;
            pp[h*3+0]=sd[0]; pp[h*3+1]=sd[1]; pp[h*3+2]=sd[2];
            pp[12+h] = a_hist[(b*NH_+h)*N_ + n];
        }
    } else {
        int i = (bid - COMBO_TOPK - COMBO_PREP)*256 + tid;
        int idx = i;
        if (idx < 256*NF_)        { (S + OFF_WPE1)[idx] = f2tff(pe_w1[idx]); }
        else if (idx < 512*NF_)   { idx -= 256*NF_;  (S + OFF_WRE1)[idx] = f2tff(re_w1[idx]); }
        else if (idx < 768*NF_)   { idx -= 512*NF_;  (S + OFF_WRE2)[idx] = f2tff(re_w2[idx]); }
        else if (idx < 1536*NF_)  { idx -= 768*NF_;  (S + OFF_WRP)[idx]  = f2tff(rp_w[idx]); }
        else if (idx < 2048*NF_)  { idx -= 1536*NF_; (S + OFF_WPP)[idx]  = f2tff(pp_w[idx]); }
        else if (idx < 2304*NF_)  { idx -= 2048*NF_; (S + OFF_WPR0)[idx] = f2tff(pr_w0[idx]); }
        else {
            // wG23[k][c] = tf32( c<256 ? rp_w[256+k][c] : rp_w[512+k][c-256] )
            idx -= 2304*NF_;                       // 0 .. 256*512-1
            int k = idx >> 9, c = idx & 511;
            float v = (c < NF_) ? rp_w[(256+k)*NF_ + c] : rp_w[(512+k)*NF_ + (c-NF_)];
            (S + OFF_WG23)[idx] = f2tff(v);
        }
    }
}

// ---------------------------------------------------------------------------
__global__ void __launch_bounds__(1024)
scan_kernel(const float* __restrict__ flag, int* __restrict__ offsets,
            int* __restrict__ Mact)
{
    __shared__ int wsum[32];
    int tid = threadIdx.x;
    int lane = tid & 31, wrp = tid >> 5;

    float v[40];
    if (tid < 1000) {
        const float4* f4 = (const float4*)(flag + tid*40);
#pragma unroll
        for (int i=0;i<10;++i) {
            float4 t = f4[i];
            v[i*4+0]=t.x; v[i*4+1]=t.y; v[i*4+2]=t.z; v[i*4+3]=t.w;
        }
    } else {
#pragma unroll
        for (int i=0;i<40;++i) v[i]=0.f;
    }
    int local[4];
    int run = 0;
#pragma unroll
    for (int q=0;q<4;++q) {
        int c = 0;
#pragma unroll
        for (int k=0;k<K_TOP;++k) c += (v[q*10+k] != 0.f);
        local[q]=run; run += c;
    }
    int inc = run;
#pragma unroll
    for (int d=1; d<32; d<<=1) {
        int t = __shfl_up_sync(0xffffffffu, inc, d);
        if (lane >= d) inc += t;
    }
    if (lane == 31) wsum[wrp] = inc;
    __syncthreads();
    if (wrp == 0) {
        int w = wsum[lane];
#pragma unroll
        for (int d=1; d<32; d<<=1) {
            int t = __shfl_up_sync(0xffffffffu, w, d);
            if (lane >= d) w += t;
        }
        wsum[lane] = w;
    }
    __syncthreads();
    int before = inc - run + (wrp ? wsum[wrp-1] : 0);
#pragma unroll
    for (int q=0;q<4;++q) {
        int node = tid*4+q;
        if (node < NODES) offsets[node] = before + local[q];
    }
    if (tid == 1023) { int tot = wsum[31]; offsets[NODES] = tot; Mact[0] = tot; }
}

// ---------------------------------------------------------------------------
__global__ void fill_kernel(const float* __restrict__ scur, const float* __restrict__ acur,
                            const int* __restrict__ send, const float* __restrict__ flag,
                            const int* __restrict__ offsets,
                            int* __restrict__ sendc, float* __restrict__ rein)
{
    int r = blockIdx.x*blockDim.x+threadIdx.x;
    if (r >= EDGES) return;
    if (flag[r] == 0.f) return;
    int node = r / K_TOP, k = r % K_TOP;
    int rank = 0;
    for (int kk = 0; kk < k; ++kk) rank += (flag[node*K_TOP+kk] != 0.f);
    int pos = offsets[node] + rank;
    int s = send[r];
    sendc[pos] = s;
    float* o = rein + (size_t)pos*5;
    o[0] = acur[node];
    o[1] = acur[s];
    o[2] = scur[node*3+0] - scur[s*3+0];
    o[3] = scur[node*3+1] - scur[s*3+1];
    o[4] = scur[node*3+2] - scur[s*3+2];
}

// ---------------------------------------------------------------------------
// direct small-K GEMM: 32 rows/block (R12-proven)
// ---------------------------------------------------------------------------
struct GDesc {
    const float* A; const float* W; const float* bias; float* C;
    const int* Mp; int Mconst; int K; int ntiles;
};

__global__ void __launch_bounds__(256)
smallk_multi(GDesc d0, GDesc d1)
{
    int bx = blockIdx.x;
    GDesc d;
    if (bx < d0.ntiles) d = d0;
    else { bx -= d0.ntiles; d = d1; }

    int M = d.Mp ? __ldg(d.Mp) : d.Mconst;
    int bm = bx * 32;
    if (bm >= M) return;
    int K = d.K;

    __shared__ float Ws[16][NF_];
    __shared__ float Asm[32][17];
    int tid = threadIdx.x;

    for (int i = tid; i < K*NF_; i += 256) Ws[i>>8][i&255] = d.W[i];
    int rows = M - bm; if (rows > 32) rows = 32;
    for (int i = tid; i < rows*K; i += 256) {
        int r = i / K, k = i % K;
        Asm[r][k] = d.A[(size_t)(bm+r)*K + k];
    }
    __syncthreads();

    float b = d.bias[tid];
    if (K == 16) {
        for (int r = 0; r < rows; ++r) {
            float acc = b;
#pragma unroll
            for (int k = 0; k < 16; ++k) acc = fmaf(Asm[r][k], Ws[k][tid], acc);
            d.C[(size_t)(bm+r)*NF_ + tid] = f2tff(fmaxf(acc, 0.f));
        }
    } else {  // K == 5
        for (int r = 0; r < rows; ++r) {
            float acc = b;
#pragma unroll
            for (int k = 0; k < 5; ++k) acc = fmaf(Asm[r][k], Ws[k][tid], acc);
            d.C[(size_t)(bm+r)*NF_ + tid] = f2tff(fmaxf(acc, 0.f));
        }
    }
}

// ---------------------------------------------------------------------------
struct TDesc {
    const float* A; const float* W; const float* bias;
    const float* add0; const float* add1; float* C;
    const int* Mp; int Mconst; int relu; int out_mode; int rt;
    const float* w1; float* outp; int ntiles;
    int nbx; int ldw; int ldc;   // column-tile count, W row stride, C row stride
};

#define SA 24
#define SB 136

// ---------------------------------------------------------------------------
// tf32 tc GEMM, 128x128 tiles (pre-rounded inputs, LDS.64 A-frags)
// ---------------------------------------------------------------------------
__global__ void __launch_bounds__(256)
tc_multi(TDesc d0, TDesc d1, TDesc d2, TDesc d3)
{
    int bx = blockIdx.x;
    TDesc d;
    if (bx < d0.ntiles) d = d0;
    else { bx -= d0.ntiles;
        if (bx < d1.ntiles) d = d1;
        else { bx -= d1.ntiles;
            if (bx < d2.ntiles) d = d2;
            else { bx -= d2.ntiles; d = d3; } } }

    int M = d.Mp ? __ldg(d.Mp) : d.Mconst;
    int bm = (bx >> 1) * 128;
    if (bm >= M) return;
    int bn = (bx & 1) * 128;
    const float* A = d.A;
    const float* W = d.W;

    __shared__ unsigned As[2][128*SA];
    __shared__ unsigned Bs[2][16*SB];

    int tid = threadIdx.x;
    int wid = tid >> 5, lane = tid & 31;
    int gid = lane >> 2, tig = lane & 3;
    int warp_m = (wid & 3) * 32;
    int warp_n = (wid >> 2) * 64;

    float acc[2][8][4];
#pragma unroll
    for (int f=0;f<2;++f)
#pragma unroll
        for (int g=0;g<8;++g)
#pragma unroll
            for (int q=0;q<4;++q) acc[f][g][q]=0.f;

#define TC_LOAD(buf, k0)                                                      \
    {                                                                         \
        _Pragma("unroll")                                                     \
        for (int i = 0; i < 2; ++i) {                                         \
            int idx = tid + i * 256;                                          \
            int row = idx >> 2, kq = (idx & 3) * 4;                           \
            int gm = bm + row;                                                \
            float4 v = make_float4(0.f,0.f,0.f,0.f);                          \
            if (gm < M) v = *(const float4*)(A + (size_t)gm * NF_ + (k0) + kq);\
            int pb = (kq & 8) + ((kq & 4) >> 2);                              \
            As[buf][row*SA + pb + 0] = __float_as_uint(v.x);                  \
            As[buf][row*SA + pb + 2] = __float_as_uint(v.y);                  \
            As[buf][row*SA + pb + 4] = __float_as_uint(v.z);                  \
            As[buf][row*SA + pb + 6] = __float_as_uint(v.w);                  \
        }                                                                     \
        _Pragma("unroll")                                                     \
        for (int i = 0; i < 2; ++i) {                                         \
            int idx = tid + i * 256;                                          \
            int kk = idx >> 5, nn = (idx & 31) * 4;                           \
            float4 v = *(const float4*)(W + (size_t)((k0)+kk) * NF_ + bn + nn);\
            Bs[buf][kk*SB + nn + 0] = __float_as_uint(v.x);                   \
            Bs[buf][kk*SB + nn + 1] = __float_as_uint(v.y);                   \
            Bs[buf][kk*SB + nn + 2] = __float_as_uint(v.z);                   \
            Bs[buf][kk*SB + nn + 3] = __float_as_uint(v.w);                   \
        }                                                                     \
    }

    TC_LOAD(0, 0);
    __syncthreads();

#pragma unroll 1
    for (int t = 0; t < 16; ++t) {
        int cur = t & 1, nxt = cur ^ 1;
        if (t + 1 < 16) TC_LOAD(nxt, (t + 1) * 16);
#pragma unroll
        for (int ks = 0; ks < 2; ++ks) {
            int kb = ks * 8;
            unsigned a[2][4], bfr[8][2];
#pragma unroll
            for (int f = 0; f < 2; ++f) {
                int rb = warp_m + f*16;
                uint2 t0 = *(const uint2*)&As[cur][(rb+gid  )*SA + kb + 2*tig];
                uint2 t1 = *(const uint2*)&As[cur][(rb+gid+8)*SA + kb + 2*tig];
                a[f][0] = t0.x; a[f][2] = t0.y;
                a[f][1] = t1.x; a[f][3] = t1.y;
            }
#pragma unroll
            for (int g = 0; g < 8; ++g) {
                int nb = warp_n + g*8;
                bfr[g][0] = Bs[cur][(kb+tig  )*SB + nb + gid];
                bfr[g][1] = Bs[cur][(kb+tig+4)*SB + nb + gid];
            }
#pragma unroll
            for (int f = 0; f < 2; ++f)
#pragma unroll
                for (int g = 0; g < 8; ++g) {
                    asm volatile(
                        "mma.sync.aligned.m16n8k8.row.col.f32.tf32.tf32.f32 "
                        "{%0,%1,%2,%3},{%4,%5,%6,%7},{%8,%9},{%0,%1,%2,%3};"
                        : "+f"(acc[f][g][0]), "+f"(acc[f][g][1]),
                          "+f"(acc[f][g][2]), "+f"(acc[f][g][3])
                        : "r"(a[f][0]), "r"(a[f][1]), "r"(a[f][2]), "r"(a[f][3]),
                          "r"(bfr[g][0]), "r"(bfr[g][1]));
                }
        }
        __syncthreads();
    }
#undef TC_LOAD

#pragma unroll
    for (int f = 0; f < 2; ++f) {
        int r0 = bm + warp_m + f*16 + gid;
        int r1 = r0 + 8;
#pragma unroll
        for (int g = 0; g < 8; ++g) {
            int ccol = bn + warp_n + g*8 + tig*2;
            float b0 = d.bias ? d.bias[ccol] : 0.f;
            float b1 = d.bias ? d.bias[ccol+1] : 0.f;
            if (r0 < M) {
                size_t off = (size_t)r0 * NF_ + ccol;
                float v0 = acc[f][g][0] + b0;
                float v1 = acc[f][g][1] + b1;
                if (d.add0) { v0 += d.add0[off]; v1 += d.add0[off+1]; }
                if (d.add1) { v0 += d.add1[off]; v1 += d.add1[off+1]; }
                if (d.relu) { v0 = fmaxf(v0,0.f); v1 = fmaxf(v1,0.f); }
                if (d.rt)   { v0 = f2tff(v0); v1 = f2tff(v1); }
                *(float2*)(d.C + off) = make_float2(v0, v1);
            }
            if (r1 < M) {
                size_t off = (size_t)r1 * NF_ + ccol;
                float v0 = acc[f][g][2] + b0;
                float v1 = acc[f][g][3] + b1;
                if (d.add0) { v0 += d.add0[off]; v1 += d.add0[off+1]; }
                if (d.add1) { v0 += d.add1[off]; v1 += d.add1[off+1]; }
                if (d.relu) { v0 = fmaxf(v0,0.f); v1 = fmaxf(v1,0.f); }
                if (d.rt)   { v0 = f2tff(v0); v1 = f2tff(v1); }
                *(float2*)(d.C + off) = make_float2(v0, v1);
            }
        }
    }
}

// ---------------------------------------------------------------------------
// tf32 tc GEMM, 64x128 tiles, stride-generalized (nbx column tiles, ldw, ldc)
// ---------------------------------------------------------------------------
__global__ void __launch_bounds__(256)
tc64_multi(TDesc d0, TDesc d1)
{
    int bx = blockIdx.x;
    TDesc d;
    if (bx < d0.ntiles) d = d0;
    else { bx -= d0.ntiles; d = d1; }

    int M = d.Mconst;
    int nbx = d.nbx;
    int bm = (bx / nbx) * 64;
    if (bm >= M) return;
    int bn = (bx % nbx) * 128;
    int ldw = d.ldw, ldc = d.ldc;
    const float* A = d.A;
    const float* W = d.W;

    __shared__ unsigned As[2][64*SA];
    __shared__ unsigned Bs[2][16*SB];

    int tid = threadIdx.x;
    int wid = tid >> 5, lane = tid & 31;
    int gid = lane >> 2, tig = lane & 3;
    int warp_m = (wid & 1) * 32;
    int warp_n = (wid >> 1) * 32;

    float acc[2][4][4];
#pragma unroll
    for (int f=0;f<2;++f)
#pragma unroll
        for (int g=0;g<4;++g)
#pragma unroll
            for (int q=0;q<4;++q) acc[f][g][q]=0.f;

#define TC64_LOAD(buf, k0)                                                    \
    {                                                                         \
        {                                                                     \
            int row = tid >> 2, kq = (tid & 3) * 4;                           \
            int gm = bm + row;                                                \
            float4 v = make_float4(0.f,0.f,0.f,0.f);                          \
            if (gm < M) v = *(const float4*)(A + (size_t)gm * NF_ + (k0) + kq);\
            int pb = (kq & 8) + ((kq & 4) >> 2);                              \
            As[buf][row*SA + pb + 0] = __float_as_uint(v.x);                  \
            As[buf][row*SA + pb + 2] = __float_as_uint(v.y);                  \
            As[buf][row*SA + pb + 4] = __float_as_uint(v.z);                  \
            As[buf][row*SA + pb + 6] = __float_as_uint(v.w);                  \
        }                                                                     \
        _Pragma("unroll")                                                     \
        for (int i = 0; i < 2; ++i) {                                         \
            int idx = tid + i * 256;                                          \
            int kk = idx >> 5, nn = (idx & 31) * 4;                           \
            float4 v = *(const float4*)(W + (size_t)((k0)+kk) * ldw + bn + nn);\
            Bs[buf][kk*SB + nn + 0] = __float_as_uint(v.x);                   \
            Bs[buf][kk*SB + nn + 1] = __float_as_uint(v.y);                   \
            Bs[buf][kk*SB + nn + 2] = __float_as_uint(v.z);                   \
            Bs[buf][kk*SB + nn + 3] = __float_as_uint(v.w);                   \
        }                                                                     \
    }

    TC64_LOAD(0, 0);
    __syncthreads();

#pragma unroll 1
    for (int t = 0; t < 16; ++t) {
        int cur = t & 1, nxt = cur ^ 1;
        if (t + 1 < 16) TC64_LOAD(nxt, (t + 1) * 16);
#pragma unroll
        for (int ks = 0; ks < 2; ++ks) {
            int kb = ks * 8;
            unsigned a[2][4], bfr[4][2];
#pragma unroll
            for (int f = 0; f < 2; ++f) {
                int rb = warp_m + f*16;
                uint2 t0 = *(const uint2*)&As[cur][(rb+gid  )*SA + kb + 2*tig];
                uint2 t1 = *(const uint2*)&As[cur][(rb+gid+8)*SA + kb + 2*tig];
                a[f][0] = t0.x; a[f][2] = t0.y;
                a[f][1] = t1.x; a[f][3] = t1.y;
            }
#pragma unroll
            for (int g = 0; g < 4; ++g) {
                int nb = warp_n + g*8;
                bfr[g][0] = Bs[cur][(kb+tig  )*SB + nb + gid];
                bfr[g][1] = Bs[cur][(kb+tig+4)*SB + nb + gid];
            }
#pragma unroll
            for (int f = 0; f < 2; ++f)
#pragma unroll
                for (int g = 0; g < 4; ++g) {
                    asm volatile(
                        "mma.sync.aligned.m16n8k8.row.col.f32.tf32.tf32.f32 "
                        "{%0,%1,%2,%3},{%4,%5,%6,%7},{%8,%9},{%0,%1,%2,%3};"
                        : "+f"(acc[f][g][0]), "+f"(acc[f][g][1]),
                          "+f"(acc[f][g][2]), "+f"(acc[f][g][3])
                        : "r"(a[f][0]), "r"(a[f][1]), "r"(a[f][2]), "r"(a[f][3]),
                          "r"(bfr[g][0]), "r"(bfr[g][1]));
                }
        }
        __syncthreads();
    }
#undef TC64_LOAD

    if (!d.out_mode) {
#pragma unroll
        for (int f = 0; f < 2; ++f) {
            int r0 = bm + warp_m + f*16 + gid;
            int r1 = r0 + 8;
#pragma unroll
            for (int g = 0; g < 4; ++g) {
                int ccol = bn + warp_n + g*8 + tig*2;
                float b0 = d.bias ? d.bias[ccol] : 0.f;
                float b1 = d.bias ? d.bias[ccol+1] : 0.f;
                if (r0 < M) {
                    size_t off = (size_t)r0 * ldc + ccol;
                    float v0 = acc[f][g][0] + b0;
                    float v1 = acc[f][g][1] + b1;
                    if (d.add0) { v0 += d.add0[off]; v1 += d.add0[off+1]; }
                    if (d.add1) { v0 += d.add1[off]; v1 += d.add1[off+1]; }
                    if (d.relu) { v0 = fmaxf(v0,0.f); v1 = fmaxf(v1,0.f); }
                    if (d.rt)   { v0 = f2tff(v0); v1 = f2tff(v1); }
                    *(float2*)(d.C + off) = make_float2(v0, v1);
                }
                if (r1 < M) {
                    size_t off = (size_t)r1 * ldc + ccol;
                    float v0 = acc[f][g][2] + b0;
                    float v1 = acc[f][g][3] + b1;
                    if (d.add0) { v0 += d.add0[off]; v1 += d.add0[off+1]; }
                    if (d.add1) { v0 += d.add1[off]; v1 += d.add1[off+1]; }
                    if (d.relu) { v0 = fmaxf(v0,0.f); v1 = fmaxf(v1,0.f); }
                    if (d.rt)   { v0 = f2tff(v0); v1 = f2tff(v1); }
                    *(float2*)(d.C + off) = make_float2(v0, v1);
                }
            }
        }
    } else {
#pragma unroll
        for (int f = 0; f < 2; ++f) {
            int r0 = bm + warp_m + f*16 + gid;
            int r1 = r0 + 8;
            float p0[3] = {0.f,0.f,0.f};
            float p1[3] = {0.f,0.f,0.f};
#pragma unroll
            for (int g = 0; g < 4; ++g) {
                int ccol = bn + warp_n + g*8 + tig*2;
#pragma unroll
                for (int c = 0; c < 2; ++c) {
                    int col = ccol + c;
                    float w0 = __ldg(d.w1 + col*3 + 0);
                    float wv = __ldg(d.w1 + col*3 + 1);
                    float w2 = __ldg(d.w1 + col*3 + 2);
                    float bb = d.bias[col];
                    float v0 = fmaxf(acc[f][g][0+c] + bb, 0.f);
                    float v1 = fmaxf(acc[f][g][2+c] + bb, 0.f);
                    p0[0]=fmaf(v0,w0,p0[0]); p0[1]=fmaf(v0,wv,p0[1]); p0[2]=fmaf(v0,w2,p0[2]);
                    p1[0]=fmaf(v1,w0,p1[0]); p1[1]=fmaf(v1,wv,p1[1]); p1[2]=fmaf(v1,w2,p1[2]);
                }
            }
#pragma unroll
            for (int j = 0; j < 3; ++j) {
                p0[j] += __shfl_xor_sync(0xffffffffu, p0[j], 1);
                p0[j] += __shfl_xor_sync(0xffffffffu, p0[j], 2);
                p1[j] += __shfl_xor_sync(0xffffffffu, p1[j], 1);
                p1[j] += __shfl_xor_sync(0xffffffffu, p1[j], 2);
            }
            if (tig == 0) {
                if (r0 < M) {
                    atomicAdd(d.outp + r0*3 + 0, p0[0]);
                    atomicAdd(d.outp + r0*3 + 1, p0[1]);
                    atomicAdd(d.outp + r0*3 + 2, p0[2]);
                }
                if (r1 < M) {
                    atomicAdd(d.outp + r1*3 + 0, p1[0]);
                    atomicAdd(d.outp + r1*3 + 1, p1[1]);
                    atomicAdd(d.outp + r1*3 + 2, p1[2]);
                }
            }
        }
    }
}

// ---------------------------------------------------------------------------
// agg over G23 (stride 512): agg[n,c] = sum relu(base[e,c]+G23[n,c]+G23[s,256+c])
// ---------------------------------------------------------------------------
__global__ void agg_kernel(const float* __restrict__ base, const float* __restrict__ G23,
                           const int* __restrict__ sendc, const int* __restrict__ offsets,
                           float* __restrict__ agg)
{
    int w = blockIdx.x*blockDim.x + threadIdx.x;
    if (w >= NODES*64) return;
    int node = w >> 6, q = (w & 63) * 4;
    float4 g2 = *(const float4*)(G23 + (size_t)node*(2*NF_) + q);
    int e0 = offsets[node], e1 = offsets[node+1];
    float4 a = make_float4(0.f,0.f,0.f,0.f);
    for (int e = e0; e < e1; ++e) {
        float4 bs = *(const float4*)(base + (size_t)e*NF_ + q);
        float4 g3 = *(const float4*)(G23 + (size_t)sendc[e]*(2*NF_) + NF_ + q);
        a.x += fmaxf(bs.x + g2.x + g3.x, 0.f);
        a.y += fmaxf(bs.y + g2.y + g3.y, 0.f);
        a.z += fmaxf(bs.z + g2.z + g3.z, 0.f);
        a.w += fmaxf(bs.w + g2.w + g3.w, 0.f);
    }
    a.x = f2tff(a.x); a.y = f2tff(a.y); a.z = f2tff(a.z); a.w = f2tff(a.w);
    *(float4*)(agg + (size_t)node*NF_ + q) = a;
}

// ---------------------------------------------------------------------------
extern "C" void kernel_launch(void* const* d_in, const int* in_sizes, int n_in,
                              void* d_out, int out_size)
{
    const float* a_hist =(const float*)d_in[0];
    const float* s_hist =(const float*)d_in[1];
    const float* s_delta=(const float*)d_in[2];
    const float* pe_w0=(const float*)d_in[3];  const float* pe_b0=(const float*)d_in[4];
    const float* pe_w1=(const float*)d_in[5];  const float* pe_b1=(const float*)d_in[6];
    const float* re_w0=(const float*)d_in[7];  const float* re_b0=(const float*)d_in[8];
    const float* re_w1=(const float*)d_in[9];  const float* re_b1=(const float*)d_in[10];
    const float* re_w2=(const float*)d_in[11]; const float* re_b2=(const float*)d_in[12];
    const float* rp_w =(const float*)d_in[13]; const float* rp_b =(const float*)d_in[14];
    const float* pp_w =(const float*)d_in[15]; const float* pp_b =(const float*)d_in[16];
    const float* pr_w0=(const float*)d_in[17]; const float* pr_b0=(const float*)d_in[18];
    const float* pr_w1=(const float*)d_in[19]; const float* pr_b1=(const float*)d_in[20];
    float* out = (float*)d_out;

    void* sp;   cudaGetSymbolAddress(&sp, g_scratch);
    void* p1;   cudaGetSymbolAddress(&p1, g_send);
    void* p2;   cudaGetSymbolAddress(&p2, g_sendc);
    void* p3;   cudaGetSymbolAddress(&p3, g_offsets);
    void* p4;   cudaGetSymbolAddress(&p4, g_Mact);
    float* S = (float*)sp;
    int* send    = (int*)p1;
    int* sendc   = (int*)p2;
    int* offsets = (int*)p3;
    int* Mact    = (int*)p4;

    float* scur=S+OFF_SCUR; float* acur=S+OFF_ACUR; float* pein=S+OFF_PEIN;
    float* flag=S+OFF_FLAG; float* rein=S+OFF_REIN;
    float* bufA=S+OFF_BUFA; float* bufB=S+OFF_BUFB; float* base=S+OFF_BASE;
    float* peh =S+OFF_PEH;  float* pe  =S+OFF_PE;   float* G23 =S+OFF_G23;
    float* agg =S+OFF_AGG;  float* ppc =S+OFF_PPC;
    float* wPE1=S+OFF_WPE1; float* wRE1=S+OFF_WRE1; float* wRE2=S+OFF_WRE2;
    float* wRP =S+OFF_WRP;  float* wPP =S+OFF_WPP;  float* wPR0=S+OFF_WPR0;
    float* wG23=S+OFF_WG23;

    const int NT_NODE   = ((NODES+127)/128)*2;  // 64
    const int NT_NODE64 = ((NODES+63)/64)*2;    // 126
    const int NT_G23    = ((NODES+63)/64)*4;    // 252 (NOUT=512)
    const int NT_EDGE   = ((EDGES+127)/128)*2;  // 626 worst case

    TDesc Z = {};

    auto TD = [&](const float* A,const float* W,const float* bias,
                  const float* a0,const float* a1,float* C,
                  const int* Mp,int Mc,int relu,int rt,int nt)->TDesc {
        TDesc d; d.A=A; d.W=W; d.bias=bias; d.add0=a0; d.add1=a1; d.C=C;
        d.Mp=Mp; d.Mconst=Mc; d.relu=relu; d.out_mode=0; d.rt=rt;
        d.w1=0; d.outp=0; d.ntiles=nt; d.nbx=2; d.ldw=NF_; d.ldc=NF_;
        return d;
    };

    // combo: topk + prep + wcvt (+wG23 concat)
    combo_kernel<<<COMBO_BLOCKS,256>>>(a_hist,s_hist,s_delta,pr_b1,
                                       pe_w1,re_w1,re_w2,rp_w,pp_w,pr_w0,
                                       S, send, flag, out);
    scan_kernel<<<1,1024>>>(flag, offsets, Mact);
    fill_kernel<<<(EDGES+255)/256,256>>>(scur,acur,send,flag,offsets,sendc,rein);

    // L1: peh (K=16, node) + bufA (K=5, edges) — 32 rows/block
    {
        GDesc dA; dA.A=pein; dA.W=pe_w0; dA.bias=pe_b0; dA.C=peh;
        dA.Mp=0; dA.Mconst=NODES; dA.K=16; dA.ntiles=(NODES+31)/32;       // 125
        GDesc dB; dB.A=rein; dB.W=re_w0; dB.bias=re_b0; dB.C=bufA;
        dB.Mp=Mact; dB.Mconst=0; dB.K=5; dB.ntiles=(EDGES+31)/32;         // 1250
        smallk_multi<<<dA.ntiles+dB.ntiles,256>>>(dA,dB);
    }
    // L2: pe = relu(peh@wPE1+b) [rt]  +  bufB = relu(bufA@wRE1+b) [rt]
    {
        TDesc a = TD(peh, wPE1, pe_b1, 0,0, pe,  0, NODES, 1, 1, NT_NODE);
        TDesc b = TD(bufA, wRE1, re_b1, 0,0, bufB, Mact, 0, 1, 1, NT_EDGE);
        tc_multi<<<a.ntiles+b.ntiles,256>>>(a,b,Z,Z);
    }
    // L3: ppc + renc [rt] + G23_0 (fused G2|G3, tc64 via extra launch below)
    {
        TDesc a = TD(pe,   wPP,  pp_b,  0,0, ppc,  0, NODES, 0, 0, NT_NODE);
        TDesc b = TD(bufB, wRE2, re_b2, 0,0, bufA, Mact, 0, 1, 1, NT_EDGE);
        tc_multi<<<a.ntiles+b.ntiles,256>>>(a,b,Z,Z);
        TDesc g = TD(pe, wG23, 0, 0,0, G23, 0, NODES, 0, 0, NT_G23);
        g.nbx = 4; g.ldw = 2*NF_; g.ldc = 2*NF_;
        tc64_multi<<<g.ntiles,256>>>(g,Z);
    }
    // L4: base = renc @ wRP[0:256] + rp_b
    {
        TDesc a = TD(bufA, wRP, rp_b, 0,0, base, Mact, 0, 0, 0, NT_EDGE);
        tc_multi<<<a.ntiles,256>>>(a,Z,Z,Z);
    }

    for (int step=0; step<3; ++step) {
        agg_kernel<<<(NODES*64+255)/256,256>>>(base, G23, sendc, offsets, agg);
        TDesc j = TD(agg, wPP + 256*NF_, 0, ppc, pe, pe, 0, NODES, 1, 1, NT_NODE64);
        tc64_multi<<<j.ntiles,256>>>(j,Z);
        if (step < 2) {
            TDesc g = TD(pe, wG23, 0, 0,0, G23, 0, NODES, 0, 0, NT_G23);
            g.nbx = 4; g.ldw = 2*NF_; g.ldc = 2*NF_;
            tc64_multi<<<g.ntiles,256>>>(g,Z);
        }
    }

    // final: pr GEMM with fused 256->3 output epilogue
    {
        TDesc k = TD(pe, wPR0, pr_b0, 0,0, 0, 0, NODES, 1, 0, NT_NODE64);
        k.out_mode = 1; k.w1 = pr_w1; k.outp = out;
        tc64_multi<<<k.ntiles,256>>>(k,Z);
    }
}

// round 15
// speedup vs baseline: 1.1606x; 1.1606x over previous
#include <cuda_runtime.h>

#define B_    4
#define NH_   4
#define N_    1000
#define NF_   256
#define K_TOP 10
#define NODES (B_*N_)       // 4000
#define EDGES (B_*K_TOP*N_) // 40000

// ---- scratch layout (floats) ----
#define OFF_SCUR 0
#define OFF_ACUR (OFF_SCUR + NODES*3)
#define OFF_PEIN (OFF_ACUR + NODES)
#define OFF_FLAG (OFF_PEIN + NODES*16)
#define OFF_REIN (OFF_FLAG + EDGES)
#define OFF_BUFA (OFF_REIN + EDGES*5)
#define OFF_BUFB (OFF_BUFA + EDGES*NF_)
#define OFF_BASE (OFF_BUFB + EDGES*NF_)
#define OFF_PEH  (OFF_BASE + EDGES*NF_)
#define OFF_PE   (OFF_PEH  + NODES*NF_)
#define OFF_G2   (OFF_PE   + NODES*NF_)
#define OFF_G3   (OFF_G2   + NODES*NF_)
#define OFF_AGG  (OFF_G3   + NODES*NF_)
#define OFF_PPC  (OFF_AGG  + NODES*NF_)
#define OFF_WPE1 (OFF_PPC  + NODES*NF_)
#define OFF_WRE1 (OFF_WPE1 + NF_*NF_)
#define OFF_WRE2 (OFF_WRE1 + NF_*NF_)
#define OFF_WRP  (OFF_WRE2 + NF_*NF_)
#define OFF_WPP  (OFF_WRP  + 3*NF_*NF_)
#define OFF_WPR0 (OFF_WPP  + 2*NF_*NF_)
#define SCRATCH_TOTAL (OFF_WPR0 + NF_*NF_)

__device__ float g_scratch[SCRATCH_TOTAL];
__device__ int   g_send[EDGES];
__device__ int   g_sendc[EDGES];
__device__ int   g_offsets[NODES+1];
__device__ int   g_Mact[1];

__device__ __forceinline__ float f2tff(float x) {
    unsigned r;
    asm("cvt.rna.tf32.f32 %0, %1;" : "=r"(r) : "f"(x));
    return __uint_as_float(r);
}

// ---------------------------------------------------------------------------
// combo: topk (8-way split, 32 nodes/block) + prep + wcvt — one launch
// ---------------------------------------------------------------------------
#define COMBO_TOPK   128
#define COMBO_PREP   16
#define COMBO_WCVT   2304
#define COMBO_BLOCKS (COMBO_TOPK + COMBO_PREP + COMBO_WCVT)

__global__ void __launch_bounds__(256)
combo_kernel(const float* __restrict__ a_hist,
             const float* __restrict__ s_hist,
             const float* __restrict__ s_delta,
             const float* __restrict__ pr_b1,
             const float* __restrict__ pe_w1, const float* __restrict__ re_w1,
             const float* __restrict__ re_w2, const float* __restrict__ rp_w,
             const float* __restrict__ pp_w,  const float* __restrict__ pr_w0,
             float* __restrict__ S,
             int* __restrict__ send, float* __restrict__ flag,
             float* __restrict__ out)
{
    int bid = blockIdx.x;
    int tid = threadIdx.x;

    if (bid < COMBO_TOPK) {
        __shared__ float sx[N_], sy[N_], sz[N_];
        __shared__ unsigned char st[N_];
        __shared__ float md[256][K_TOP];
        __shared__ short mi[256][K_TOP];
        int b = bid >> 5;
        int xb = bid & 31;
        for (int j = tid; j < N_; j += 256) {
            const float* sh = s_hist + ((size_t)(b*NH_ + NH_-1)*N_ + j)*3;
            sx[j]=sh[0]; sy[j]=sh[1]; sz[j]=sh[2];
            st[j] = a_hist[(b*NH_ + NH_-1)*N_ + j] > 0.5f ? 1 : 0;
        }
        __syncthreads();
        int li = tid & 31;
        int part = tid >> 5;
        int i = xb*32 + li;
        float dv[K_TOP]; short iv[K_TOP];
#pragma unroll
        for (int t=0;t<K_TOP;++t){ dv[t]=3.0e38f; iv[t]=0; }
        if (i < N_) {
            bool ti = st[i] != 0;
            float xi=sx[i], yi=sy[i], zi=sz[i];
            int j0 = part*125, j1 = j0+125;
            for (int j=j0;j<j1;++j) {
                float dx=__fadd_rn(xi,-sx[j]), dy=__fadd_rn(yi,-sy[j]), dz=__fadd_rn(zi,-sz[j]);
                float d = __fadd_rn(__fadd_rn(__fmul_rn(dx,dx),__fmul_rn(dy,dy)),__fmul_rn(dz,dz));
                if (ti && st[j]) d = 1e10f;
                if (d < dv[K_TOP-1]) {
#pragma unroll
                    for (int t=K_TOP-1; t>=1; --t) {
                        if (d < dv[t-1])      { dv[t]=dv[t-1]; iv[t]=iv[t-1]; }
                        else if (d < dv[t])   { dv[t]=d;       iv[t]=(short)j; }
                    }
                    if (d < dv[0]) { dv[0]=d; iv[0]=(short)j; }
                }
            }
        }
#pragma unroll
        for (int t=0;t<K_TOP;++t){ md[tid][t]=dv[t]; mi[tid][t]=iv[t]; }
        __syncthreads();
        if (part == 0 && i < N_) {
            bool ti = st[i] != 0;
            int ptr[8] = {0,0,0,0,0,0,0,0};
            int gi = b*N_ + i;
#pragma unroll
            for (int t=0;t<K_TOP;++t) {
                float best = 3.5e38f; int bp = 0;
#pragma unroll
                for (int p=0;p<8;++p) {
                    float dd = md[li + p*32][ptr[p]];
                    if (dd < best) { best = dd; bp = p; }
                }
                int j = mi[li + bp*32][ptr[bp]];
                ptr[bp]++;
                int rg = gi*K_TOP + t;
                send[rg] = b*N_ + j;
                flag[rg] = (!ti && best < 0.25f) ? 1.0f : 0.0f;
            }
        }
    } else if (bid < COMBO_TOPK + COMBO_PREP) {
        int idx = (bid - COMBO_TOPK)*256 + tid;
        if (idx >= NODES) return;
        int b = idx / N_, n = idx % N_;
        float* scur = S + OFF_SCUR;
        float* acur = S + OFF_ACUR;
        float* pein = S + OFF_PEIN;
        acur[idx] = a_hist[(b*NH_ + NH_-1)*N_ + n];
        const float* sh = s_hist + ((size_t)(b*NH_ + NH_-1)*N_ + n)*3;
        float s0=sh[0], s1=sh[1], s2=sh[2];
        scur[idx*3+0]=s0; scur[idx*3+1]=s1; scur[idx*3+2]=s2;
        out[idx*3+0] = s0 + pr_b1[0];
        out[idx*3+1] = s1 + pr_b1[1];
        out[idx*3+2] = s2 + pr_b1[2];
        float* pp = pein + (size_t)idx*16;
#pragma unroll
        for (int h=0; h<NH_; ++h) {
            const float* sd = s_delta + ((size_t)(b*NH_+h)*N_ + n)*3;
            pp[h*3+0]=sd[0]; pp[h*3+1]=sd[1]; pp[h*3+2]=sd[2];
            pp[12+h] = a_hist[(b*NH_+h)*N_ + n];
        }
    } else {
        int i = (bid - COMBO_TOPK - COMBO_PREP)*256 + tid;
        int total = 2304 * NF_;
        if (i >= total) return;
        const float* src;
        float* dst;
        int idx = i;
        if (idx < 256*NF_)        { src = pe_w1;  dst = S + OFF_WPE1; }
        else if (idx < 512*NF_)   { src = re_w1;  dst = S + OFF_WRE1; idx -= 256*NF_; }
        else if (idx < 768*NF_)   { src = re_w2;  dst = S + OFF_WRE2; idx -= 512*NF_; }
        else if (idx < 1536*NF_)  { src = rp_w;   dst = S + OFF_WRP;  idx -= 768*NF_; }
        else if (idx < 2048*NF_)  { src = pp_w;   dst = S + OFF_WPP;  idx -= 1536*NF_; }
        else                      { src = pr_w0;  dst = S + OFF_WPR0; idx -= 2048*NF_; }
        dst[idx] = f2tff(src[idx]);
    }
}

// ---------------------------------------------------------------------------
__global__ void __launch_bounds__(1024)
scan_kernel(const float* __restrict__ flag, int* __restrict__ offsets,
            int* __restrict__ Mact)
{
    __shared__ int wsum[32];
    int tid = threadIdx.x;
    int lane = tid & 31, wrp = tid >> 5;

    float v[40];
    if (tid < 1000) {
        const float4* f4 = (const float4*)(flag + tid*40);
#pragma unroll
        for (int i=0;i<10;++i) {
            float4 t = f4[i];
            v[i*4+0]=t.x; v[i*4+1]=t.y; v[i*4+2]=t.z; v[i*4+3]=t.w;
        }
    } else {
#pragma unroll
        for (int i=0;i<40;++i) v[i]=0.f;
    }
    int local[4];
    int run = 0;
#pragma unroll
    for (int q=0;q<4;++q) {
        int c = 0;
#pragma unroll
        for (int k=0;k<K_TOP;++k) c += (v[q*10+k] != 0.f);
        local[q]=run; run += c;
    }
    int inc = run;
#pragma unroll
    for (int d=1; d<32; d<<=1) {
        int t = __shfl_up_sync(0xffffffffu, inc, d);
        if (lane >= d) inc += t;
    }
    if (lane == 31) wsum[wrp] = inc;
    __syncthreads();
    if (wrp == 0) {
        int w = wsum[lane];
#pragma unroll
        for (int d=1; d<32; d<<=1) {
            int t = __shfl_up_sync(0xffffffffu, w, d);
            if (lane >= d) w += t;
        }
        wsum[lane] = w;
    }
    __syncthreads();
    int before = inc - run + (wrp ? wsum[wrp-1] : 0);
#pragma unroll
    for (int q=0;q<4;++q) {
        int node = tid*4+q;
        if (node < NODES) offsets[node] = before + local[q];
    }
    if (tid == 1023) { int tot = wsum[31]; offsets[NODES] = tot; Mact[0] = tot; }
}

// ---------------------------------------------------------------------------
__global__ void fill_kernel(const float* __restrict__ scur, const float* __restrict__ acur,
                            const int* __restrict__ send, const float* __restrict__ flag,
                            const int* __restrict__ offsets,
                            int* __restrict__ sendc, float* __restrict__ rein)
{
    int r = blockIdx.x*blockDim.x+threadIdx.x;
    if (r >= EDGES) return;
    if (flag[r] == 0.f) return;
    int node = r / K_TOP, k = r % K_TOP;
    int rank = 0;
    for (int kk = 0; kk < k; ++kk) rank += (flag[node*K_TOP+kk] != 0.f);
    int pos = offsets[node] + rank;
    int s = send[r];
    sendc[pos] = s;
    float* o = rein + (size_t)pos*5;
    o[0] = acur[node];
    o[1] = acur[s];
    o[2] = scur[node*3+0] - scur[s*3+0];
    o[3] = scur[node*3+1] - scur[s*3+1];
    o[4] = scur[node*3+2] - scur[s*3+2];
}

// ---------------------------------------------------------------------------
// direct small-K GEMM: 32 rows/block (R12-proven)
// ---------------------------------------------------------------------------
struct GDesc {
    const float* A; const float* W; const float* bias; float* C;
    const int* Mp; int Mconst; int K; int ntiles;
};

__global__ void __launch_bounds__(256)
smallk_multi(GDesc d0, GDesc d1)
{
    int bx = blockIdx.x;
    GDesc d;
    if (bx < d0.ntiles) d = d0;
    else { bx -= d0.ntiles; d = d1; }

    int M = d.Mp ? __ldg(d.Mp) : d.Mconst;
    int bm = bx * 32;
    if (bm >= M) return;
    int K = d.K;

    __shared__ float Ws[16][NF_];
    __shared__ float Asm[32][17];
    int tid = threadIdx.x;

    for (int i = tid; i < K*NF_; i += 256) Ws[i>>8][i&255] = d.W[i];
    int rows = M - bm; if (rows > 32) rows = 32;
    for (int i = tid; i < rows*K; i += 256) {
        int r = i / K, k = i % K;
        Asm[r][k] = d.A[(size_t)(bm+r)*K + k];
    }
    __syncthreads();

    float b = d.bias[tid];
    if (K == 16) {
        for (int r = 0; r < rows; ++r) {
            float acc = b;
#pragma unroll
            for (int k = 0; k < 16; ++k) acc = fmaf(Asm[r][k], Ws[k][tid], acc);
            d.C[(size_t)(bm+r)*NF_ + tid] = f2tff(fmaxf(acc, 0.f));
        }
    } else {  // K == 5
        for (int r = 0; r < rows; ++r) {
            float acc = b;
#pragma unroll
            for (int k = 0; k < 5; ++k) acc = fmaf(Asm[r][k], Ws[k][tid], acc);
            d.C[(size_t)(bm+r)*NF_ + tid] = f2tff(fmaxf(acc, 0.f));
        }
    }
}

// ---------------------------------------------------------------------------
struct TDesc {
    const float* A; const float* W; const float* bias;
    const float* add0; const float* add1; float* C;
    const int* Mp; int Mconst; int relu; int out_mode; int rt;
    const float* w1; float* outp; int ntiles;
};

#define SA 24
#define SB 136

// ---------------------------------------------------------------------------
// tf32 tc GEMM, 128x128 tiles — software-pipelined: LDG(t+1) -> MMA(t) -> STS(t+1)
// ---------------------------------------------------------------------------
__global__ void __launch_bounds__(256, 2)
tc_multi(TDesc d0, TDesc d1, TDesc d2, TDesc d3)
{
    int bx = blockIdx.x;
    TDesc d;
    if (bx < d0.ntiles) d = d0;
    else { bx -= d0.ntiles;
        if (bx < d1.ntiles) d = d1;
        else { bx -= d1.ntiles;
            if (bx < d2.ntiles) d = d2;
            else { bx -= d2.ntiles; d = d3; } } }

    int M = d.Mp ? __ldg(d.Mp) : d.Mconst;
    int bm = (bx >> 1) * 128;
    if (bm >= M) return;
    int bn = (bx & 1) * 128;
    const float* A = d.A;
    const float* W = d.W;

    __shared__ unsigned As[2][128*SA];
    __shared__ unsigned Bs[2][16*SB];

    int tid = threadIdx.x;
    int wid = tid >> 5, lane = tid & 31;
    int gid = lane >> 2, tig = lane & 3;
    int warp_m = (wid & 3) * 32;
    int warp_n = (wid >> 2) * 64;

    // per-thread load coordinates (fixed across k-tiles)
    int a_row0 = tid >> 2,            a_kq = (tid & 3) * 4;
    int a_row1 = (tid + 256) >> 2;    // a_kq same ((tid+256)&3 == tid&3)
    int b_kk0 = tid >> 5,             b_nn = (tid & 31) * 4;
    int b_kk1 = (tid + 256) >> 5;
    int a_pb = (a_kq & 8) + ((a_kq & 4) >> 2);

    float4 ar0, ar1, br0, br1;

#define TCP_LDG(k0)                                                           \
    {                                                                         \
        int gm0 = bm + a_row0, gm1 = bm + a_row1;                             \
        ar0 = make_float4(0.f,0.f,0.f,0.f);                                   \
        ar1 = make_float4(0.f,0.f,0.f,0.f);                                   \
        if (gm0 < M) ar0 = *(const float4*)(A + (size_t)gm0 * NF_ + (k0) + a_kq);\
        if (gm1 < M) ar1 = *(const float4*)(A + (size_t)gm1 * NF_ + (k0) + a_kq);\
        br0 = *(const float4*)(W + (size_t)((k0)+b_kk0) * NF_ + bn + b_nn);   \
        br1 = *(const float4*)(W + (size_t)((k0)+b_kk1) * NF_ + bn + b_nn);   \
    }

#define TCP_STS(buf)                                                          \
    {                                                                         \
        As[buf][a_row0*SA + a_pb + 0] = __float_as_uint(ar0.x);               \
        As[buf][a_row0*SA + a_pb + 2] = __float_as_uint(ar0.y);               \
        As[buf][a_row0*SA + a_pb + 4] = __float_as_uint(ar0.z);               \
        As[buf][a_row0*SA + a_pb + 6] = __float_as_uint(ar0.w);               \
        As[buf][a_row1*SA + a_pb + 0] = __float_as_uint(ar1.x);               \
        As[buf][a_row1*SA + a_pb + 2] = __float_as_uint(ar1.y);               \
        As[buf][a_row1*SA + a_pb + 4] = __float_as_uint(ar1.z);               \
        As[buf][a_row1*SA + a_pb + 6] = __float_as_uint(ar1.w);               \
        Bs[buf][b_kk0*SB + b_nn + 0] = __float_as_uint(br0.x);                \
        Bs[buf][b_kk0*SB + b_nn + 1] = __float_as_uint(br0.y);                \
        Bs[buf][b_kk0*SB + b_nn + 2] = __float_as_uint(br0.z);                \
        Bs[buf][b_kk0*SB + b_nn + 3] = __float_as_uint(br0.w);                \
        Bs[buf][b_kk1*SB + b_nn + 0] = __float_as_uint(br1.x);                \
        Bs[buf][b_kk1*SB + b_nn + 1] = __float_as_uint(br1.y);                \
        Bs[buf][b_kk1*SB + b_nn + 2] = __float_as_uint(br1.z);                \
        Bs[buf][b_kk1*SB + b_nn + 3] = __float_as_uint(br1.w);                \
    }

    float acc[2][8][4];
#pragma unroll
    for (int f=0;f<2;++f)
#pragma unroll
        for (int g=0;g<8;++g)
#pragma unroll
            for (int q=0;q<4;++q) acc[f][g][q]=0.f;

    TCP_LDG(0);
    TCP_STS(0);
    __syncthreads();

#pragma unroll 1
    for (int t = 0; t < 16; ++t) {
        int cur = t & 1, nxt = cur ^ 1;
        if (t + 1 < 16) TCP_LDG((t + 1) * 16);
#pragma unroll
        for (int ks = 0; ks < 2; ++ks) {
            int kb = ks * 8;
            unsigned a[2][4], bfr[8][2];
#pragma unroll
            for (int f = 0; f < 2; ++f) {
                int rb = warp_m + f*16;
                uint2 t0 = *(const uint2*)&As[cur][(rb+gid  )*SA + kb + 2*tig];
                uint2 t1 = *(const uint2*)&As[cur][(rb+gid+8)*SA + kb + 2*tig];
                a[f][0] = t0.x; a[f][2] = t0.y;
                a[f][1] = t1.x; a[f][3] = t1.y;
            }
#pragma unroll
            for (int g = 0; g < 8; ++g) {
                int nb = warp_n + g*8;
                bfr[g][0] = Bs[cur][(kb+tig  )*SB + nb + gid];
                bfr[g][1] = Bs[cur][(kb+tig+4)*SB + nb + gid];
            }
#pragma unroll
            for (int f = 0; f < 2; ++f)
#pragma unroll
                for (int g = 0; g < 8; ++g) {
                    asm volatile(
                        "mma.sync.aligned.m16n8k8.row.col.f32.tf32.tf32.f32 "
                        "{%0,%1,%2,%3},{%4,%5,%6,%7},{%8,%9},{%0,%1,%2,%3};"
                        : "+f"(acc[f][g][0]), "+f"(acc[f][g][1]),
                          "+f"(acc[f][g][2]), "+f"(acc[f][g][3])
                        : "r"(a[f][0]), "r"(a[f][1]), "r"(a[f][2]), "r"(a[f][3]),
                          "r"(bfr[g][0]), "r"(bfr[g][1]));
                }
        }
        if (t + 1 < 16) TCP_STS(nxt);
        __syncthreads();
    }
#undef TCP_LDG
#undef TCP_STS

#pragma unroll
    for (int f = 0; f < 2; ++f) {
        int r0 = bm + warp_m + f*16 + gid;
        int r1 = r0 + 8;
#pragma unroll
        for (int g = 0; g < 8; ++g) {
            int ccol = bn + warp_n + g*8 + tig*2;
            float b0 = d.bias ? d.bias[ccol] : 0.f;
            float b1 = d.bias ? d.bias[ccol+1] : 0.f;
            if (r0 < M) {
                size_t off = (size_t)r0 * NF_ + ccol;
                float v0 = acc[f][g][0] + b0;
                float v1 = acc[f][g][1] + b1;
                if (d.add0) { v0 += d.add0[off]; v1 += d.add0[off+1]; }
                if (d.add1) { v0 += d.add1[off]; v1 += d.add1[off+1]; }
                if (d.relu) { v0 = fmaxf(v0,0.f); v1 = fmaxf(v1,0.f); }
                if (d.rt)   { v0 = f2tff(v0); v1 = f2tff(v1); }
                *(float2*)(d.C + off) = make_float2(v0, v1);
            }
            if (r1 < M) {
                size_t off = (size_t)r1 * NF_ + ccol;
                float v0 = acc[f][g][2] + b0;
                float v1 = acc[f][g][3] + b1;
                if (d.add0) { v0 += d.add0[off]; v1 += d.add0[off+1]; }
                if (d.add1) { v0 += d.add1[off]; v1 += d.add1[off+1]; }
                if (d.relu) { v0 = fmaxf(v0,0.f); v1 = fmaxf(v1,0.f); }
                if (d.rt)   { v0 = f2tff(v0); v1 = f2tff(v1); }
                *(float2*)(d.C + off) = make_float2(v0, v1);
            }
        }
    }
}

// ---------------------------------------------------------------------------
// tf32 tc GEMM, 64x128 tiles — software-pipelined
// ---------------------------------------------------------------------------
__global__ void __launch_bounds__(256, 2)
tc64_multi(TDesc d0, TDesc d1)
{
    int bx = blockIdx.x;
    TDesc d;
    if (bx < d0.ntiles) d = d0;
    else { bx -= d0.ntiles; d = d1; }

    int M = d.Mconst;
    int bm = (bx >> 1) * 64;
    if (bm >= M) return;
    int bn = (bx & 1) * 128;
    const float* A = d.A;
    const float* W = d.W;

    __shared__ unsigned As[2][64*SA];
    __shared__ unsigned Bs[2][16*SB];

    int tid = threadIdx.x;
    int wid = tid >> 5, lane = tid & 31;
    int gid = lane >> 2, tig = lane & 3;
    int warp_m = (wid & 1) * 32;
    int warp_n = (wid >> 1) * 32;

    int a_row = tid >> 2, a_kq = (tid & 3) * 4;
    int b_kk0 = tid >> 5, b_nn = (tid & 31) * 4;
    int b_kk1 = (tid + 256) >> 5;
    int a_pb = (a_kq & 8) + ((a_kq & 4) >> 2);

    float4 ar0, br0, br1;

#define TCP64_LDG(k0)                                                         \
    {                                                                         \
        int gm = bm + a_row;                                                  \
        ar0 = make_float4(0.f,0.f,0.f,0.f);                                   \
        if (gm < M) ar0 = *(const float4*)(A + (size_t)gm * NF_ + (k0) + a_kq);\
        br0 = *(const float4*)(W + (size_t)((k0)+b_kk0) * NF_ + bn + b_nn);   \
        br1 = *(const float4*)(W + (size_t)((k0)+b_kk1) * NF_ + bn + b_nn);   \
    }

#define TCP64_STS(buf)                                                        \
    {                                                                         \
        As[buf][a_row*SA + a_pb + 0] = __float_as_uint(ar0.x);                \
        As[buf][a_row*SA + a_pb + 2] = __float_as_uint(ar0.y);                \
        As[buf][a_row*SA + a_pb + 4] = __float_as_uint(ar0.z);                \
        As[buf][a_row*SA + a_pb + 6] = __float_as_uint(ar0.w);                \
        Bs[buf][b_kk0*SB + b_nn + 0] = __float_as_uint(br0.x);                \
        Bs[buf][b_kk0*SB + b_nn + 1] = __float_as_uint(br0.y);                \
        Bs[buf][b_kk0*SB + b_nn + 2] = __float_as_uint(br0.z);                \
        Bs[buf][b_kk0*SB + b_nn + 3] = __float_as_uint(br0.w);                \
        Bs[buf][b_kk1*SB + b_nn + 0] = __float_as_uint(br1.x);                \
        Bs[buf][b_kk1*SB + b_nn + 1] = __float_as_uint(br1.y);                \
        Bs[buf][b_kk1*SB + b_nn + 2] = __float_as_uint(br1.z);                \
        Bs[buf][b_kk1*SB + b_nn + 3] = __float_as_uint(br1.w);                \
    }

    float acc[2][4][4];
#pragma unroll
    for (int f=0;f<2;++f)
#pragma unroll
        for (int g=0;g<4;++g)
#pragma unroll
            for (int q=0;q<4;++q) acc[f][g][q]=0.f;

    TCP64_LDG(0);
    TCP64_STS(0);
    __syncthreads();

#pragma unroll 1
    for (int t = 0; t < 16; ++t) {
        int cur = t & 1, nxt = cur ^ 1;
        if (t + 1 < 16) TCP64_LDG((t + 1) * 16);
#pragma unroll
        for (int ks = 0; ks < 2; ++ks) {
            int kb = ks * 8;
            unsigned a[2][4], bfr[4][2];
#pragma unroll
            for (int f = 0; f < 2; ++f) {
                int rb = warp_m + f*16;
                uint2 t0 = *(const uint2*)&As[cur][(rb+gid  )*SA + kb + 2*tig];
                uint2 t1 = *(const uint2*)&As[cur][(rb+gid+8)*SA + kb + 2*tig];
                a[f][0] = t0.x; a[f][2] = t0.y;
                a[f][1] = t1.x; a[f][3] = t1.y;
            }
#pragma unroll
            for (int g = 0; g < 4; ++g) {
                int nb = warp_n + g*8;
                bfr[g][0] = Bs[cur][(kb+tig  )*SB + nb + gid];
                bfr[g][1] = Bs[cur][(kb+tig+4)*SB + nb + gid];
            }
#pragma unroll
            for (int f = 0; f < 2; ++f)
#pragma unroll
                for (int g = 0; g < 4; ++g) {
                    asm volatile(
                        "mma.sync.aligned.m16n8k8.row.col.f32.tf32.tf32.f32 "
                        "{%0,%1,%2,%3},{%4,%5,%6,%7},{%8,%9},{%0,%1,%2,%3};"
                        : "+f"(acc[f][g][0]), "+f"(acc[f][g][1]),
                          "+f"(acc[f][g][2]), "+f"(acc[f][g][3])
                        : "r"(a[f][0]), "r"(a[f][1]), "r"(a[f][2]), "r"(a[f][3]),
                          "r"(bfr[g][0]), "r"(bfr[g][1]));
                }
        }
        if (t + 1 < 16) TCP64_STS(nxt);
        __syncthreads();
    }
#undef TCP64_LDG
#undef TCP64_STS

    if (!d.out_mode) {
#pragma unroll
        for (int f = 0; f < 2; ++f) {
            int r0 = bm + warp_m + f*16 + gid;
            int r1 = r0 + 8;
#pragma unroll
            for (int g = 0; g < 4; ++g) {
                int ccol = bn + warp_n + g*8 + tig*2;
                float b0 = d.bias ? d.bias[ccol] : 0.f;
                float b1 = d.bias ? d.bias[ccol+1] : 0.f;
                if (r0 < M) {
                    size_t off = (size_t)r0 * NF_ + ccol;
                    float v0 = acc[f][g][0] + b0;
                    float v1 = acc[f][g][1] + b1;
                    if (d.add0) { v0 += d.add0[off]; v1 += d.add0[off+1]; }
                    if (d.add1) { v0 += d.add1[off]; v1 += d.add1[off+1]; }
                    if (d.relu) { v0 = fmaxf(v0,0.f); v1 = fmaxf(v1,0.f); }
                    if (d.rt)   { v0 = f2tff(v0); v1 = f2tff(v1); }
                    *(float2*)(d.C + off) = make_float2(v0, v1);
                }
                if (r1 < M) {
                    size_t off = (size_t)r1 * NF_ + ccol;
                    float v0 = acc[f][g][2] + b0;
                    float v1 = acc[f][g][3] + b1;
                    if (d.add0) { v0 += d.add0[off]; v1 += d.add0[off+1]; }
                    if (d.add1) { v0 += d.add1[off]; v1 += d.add1[off+1]; }
                    if (d.relu) { v0 = fmaxf(v0,0.f); v1 = fmaxf(v1,0.f); }
                    if (d.rt)   { v0 = f2tff(v0); v1 = f2tff(v1); }
                    *(float2*)(d.C + off) = make_float2(v0, v1);
                }
            }
        }
    } else {
#pragma unroll
        for (int f = 0; f < 2; ++f) {
            int r0 = bm + warp_m + f*16 + gid;
            int r1 = r0 + 8;
            float p0[3] = {0.f,0.f,0.f};
            float p1[3] = {0.f,0.f,0.f};
#pragma unroll
            for (int g = 0; g < 4; ++g) {
                int ccol = bn + warp_n + g*8 + tig*2;
#pragma unroll
                for (int c = 0; c < 2; ++c) {
                    int col = ccol + c;
                    float w0 = __ldg(d.w1 + col*3 + 0);
                    float wv = __ldg(d.w1 + col*3 + 1);
                    float w2 = __ldg(d.w1 + col*3 + 2);
                    float bb = d.bias[col];
                    float v0 = fmaxf(acc[f][g][0+c] + bb, 0.f);
                    float v1 = fmaxf(acc[f][g][2+c] + bb, 0.f);
                    p0[0]=fmaf(v0,w0,p0[0]); p0[1]=fmaf(v0,wv,p0[1]); p0[2]=fmaf(v0,w2,p0[2]);
                    p1[0]=fmaf(v1,w0,p1[0]); p1[1]=fmaf(v1,wv,p1[1]); p1[2]=fmaf(v1,w2,p1[2]);
                }
            }
#pragma unroll
            for (int j = 0; j < 3; ++j) {
                p0[j] += __shfl_xor_sync(0xffffffffu, p0[j], 1);
                p0[j] += __shfl_xor_sync(0xffffffffu, p0[j], 2);
                p1[j] += __shfl_xor_sync(0xffffffffu, p1[j], 1);
                p1[j] += __shfl_xor_sync(0xffffffffu, p1[j], 2);
            }
            if (tig == 0) {
                if (r0 < M) {
                    atomicAdd(d.outp + r0*3 + 0, p0[0]);
                    atomicAdd(d.outp + r0*3 + 1, p0[1]);
                    atomicAdd(d.outp + r0*3 + 2, p0[2]);
                }
                if (r1 < M) {
                    atomicAdd(d.outp + r1*3 + 0, p1[0]);
                    atomicAdd(d.outp + r1*3 + 1, p1[1]);
                    atomicAdd(d.outp + r1*3 + 2, p1[2]);
                }
            }
        }
    }
}

// ---------------------------------------------------------------------------
// agg (R12 form): agg[n,c] = sum relu(base[e,c] + G2[n,c] + G3[send,c])
// ---------------------------------------------------------------------------
__global__ void agg_kernel(const float* __restrict__ base, const float* __restrict__ G2,
                           const float* __restrict__ G3,
                           const int* __restrict__ sendc, const int* __restrict__ offsets,
                           float* __restrict__ agg)
{
    int w = blockIdx.x*blockDim.x + threadIdx.x;
    if (w >= NODES*64) return;
    int node = w >> 6, q = (w & 63) * 4;
    float4 g2 = *(const float4*)(G2 + (size_t)node*NF_ + q);
    int e0 = offsets[node], e1 = offsets[node+1];
    float4 a = make_float4(0.f,0.f,0.f,0.f);
    for (int e = e0; e < e1; ++e) {
        float4 bs = *(const float4*)(base + (size_t)e*NF_ + q);
        float4 g3 = *(const float4*)(G3 + (size_t)sendc[e]*NF_ + q);
        a.x += fmaxf(bs.x + g2.x + g3.x, 0.f);
        a.y += fmaxf(bs.y + g2.y + g3.y, 0.f);
        a.z += fmaxf(bs.z + g2.z + g3.z, 0.f);
        a.w += fmaxf(bs.w + g2.w + g3.w, 0.f);
    }
    a.x = f2tff(a.x); a.y = f2tff(a.y); a.z = f2tff(a.z); a.w = f2tff(a.w);
    *(float4*)(agg + (size_t)node*NF_ + q) = a;
}

// ---------------------------------------------------------------------------
extern "C" void kernel_launch(void* const* d_in, const int* in_sizes, int n_in,
                              void* d_out, int out_size)
{
    const float* a_hist =(const float*)d_in[0];
    const float* s_hist =(const float*)d_in[1];
    const float* s_delta=(const float*)d_in[2];
    const float* pe_w0=(const float*)d_in[3];  const float* pe_b0=(const float*)d_in[4];
    const float* pe_w1=(const float*)d_in[5];  const float* pe_b1=(const float*)d_in[6];
    const float* re_w0=(const float*)d_in[7];  const float* re_b0=(const float*)d_in[8];
    const float* re_w1=(const float*)d_in[9];  const float* re_b1=(const float*)d_in[10];
    const float* re_w2=(const float*)d_in[11]; const float* re_b2=(const float*)d_in[12];
    const float* rp_w =(const float*)d_in[13]; const float* rp_b =(const float*)d_in[14];
    const float* pp_w =(const float*)d_in[15]; const float* pp_b =(const float*)d_in[16];
    const float* pr_w0=(const float*)d_in[17]; const float* pr_b0=(const float*)d_in[18];
    const float* pr_w1=(const float*)d_in[19]; const float* pr_b1=(const float*)d_in[20];
    float* out = (float*)d_out;

    void* sp;   cudaGetSymbolAddress(&sp, g_scratch);
    void* p1;   cudaGetSymbolAddress(&p1, g_send);
    void* p2;   cudaGetSymbolAddress(&p2, g_sendc);
    void* p3;   cudaGetSymbolAddress(&p3, g_offsets);
    void* p4;   cudaGetSymbolAddress(&p4, g_Mact);
    float* S = (float*)sp;
    int* send    = (int*)p1;
    int* sendc   = (int*)p2;
    int* offsets = (int*)p3;
    int* Mact    = (int*)p4;

    float* scur=S+OFF_SCUR; float* acur=S+OFF_ACUR; float* pein=S+OFF_PEIN;
    float* flag=S+OFF_FLAG; float* rein=S+OFF_REIN;
    float* bufA=S+OFF_BUFA; float* bufB=S+OFF_BUFB; float* base=S+OFF_BASE;
    float* peh =S+OFF_PEH;  float* pe  =S+OFF_PE;   float* G2  =S+OFF_G2;
    float* G3  =S+OFF_G3;   float* agg =S+OFF_AGG;  float* ppc =S+OFF_PPC;
    float* wPE1=S+OFF_WPE1; float* wRE1=S+OFF_WRE1; float* wRE2=S+OFF_WRE2;
    float* wRP =S+OFF_WRP;  float* wPP =S+OFF_WPP;  float* wPR0=S+OFF_WPR0;

    const int NT_NODE   = ((NODES+127)/128)*2;  // 64
    const int NT_NODE64 = ((NODES+63)/64)*2;    // 126
    const int NT_EDGE   = ((EDGES+127)/128)*2;  // 626 worst case

    TDesc Z = {};

    auto TD = [&](const float* A,const float* W,const float* bias,
                  const float* a0,const float* a1,float* C,
                  const int* Mp,int Mc,int relu,int rt,int nt)->TDesc {
        TDesc d; d.A=A; d.W=W; d.bias=bias; d.add0=a0; d.add1=a1; d.C=C;
        d.Mp=Mp; d.Mconst=Mc; d.relu=relu; d.out_mode=0; d.rt=rt;
        d.w1=0; d.outp=0; d.ntiles=nt;
        return d;
    };

    // combo: topk + prep + wcvt (all input-only)
    combo_kernel<<<COMBO_BLOCKS,256>>>(a_hist,s_hist,s_delta,pr_b1,
                                       pe_w1,re_w1,re_w2,rp_w,pp_w,pr_w0,
                                       S, send, flag, out);
    scan_kernel<<<1,1024>>>(flag, offsets, Mact);
    fill_kernel<<<(EDGES+255)/256,256>>>(scur,acur,send,flag,offsets,sendc,rein);

    // L1: peh (K=16, node) + bufA (K=5, edges) — 32 rows/block
    {
        GDesc dA; dA.A=pein; dA.W=pe_w0; dA.bias=pe_b0; dA.C=peh;
        dA.Mp=0; dA.Mconst=NODES; dA.K=16; dA.ntiles=(NODES+31)/32;       // 125
        GDesc dB; dB.A=rein; dB.W=re_w0; dB.bias=re_b0; dB.C=bufA;
        dB.Mp=Mact; dB.Mconst=0; dB.K=5; dB.ntiles=(EDGES+31)/32;         // 1250
        smallk_multi<<<dA.ntiles+dB.ntiles,256>>>(dA,dB);
    }
    // L2: pe = relu(peh@wPE1+b) [rt]  +  bufB = relu(bufA@wRE1+b) [rt]
    {
        TDesc a = TD(peh, wPE1, pe_b1, 0,0, pe,  0, NODES, 1, 1, NT_NODE);
        TDesc b = TD(bufA, wRE1, re_b1, 0,0, bufB, Mact, 0, 1, 1, NT_EDGE);
        tc_multi<<<a.ntiles+b.ntiles,256>>>(a,b,Z,Z);
    }
    // L3: ppc + renc [rt] + G2_0 + G3_0   (R12 packing: 818 tiles)
    {
        TDesc a = TD(pe,   wPP,  pp_b,  0,0, ppc,  0, NODES, 0, 0, NT_NODE);
        TDesc b = TD(bufB, wRE2, re_b2, 0,0, bufA, Mact, 0, 1, 1, NT_EDGE);
        TDesc c = TD(pe, wRP + 256*NF_, 0, 0,0, G2, 0, NODES, 0, 0, NT_NODE);
        TDesc d = TD(pe, wRP + 512*NF_, 0, 0,0, G3, 0, NODES, 0, 0, NT_NODE);
        tc_multi<<<a.ntiles+b.ntiles+c.ntiles+d.ntiles,256>>>(a,b,c,d);
    }
    // L4: base = renc @ wRP[0:256] + rp_b   (626 tiles)
    {
        TDesc a = TD(bufA, wRP, rp_b, 0,0, base, Mact, 0, 0, 0, NT_EDGE);
        tc_multi<<<a.ntiles,256>>>(a,Z,Z,Z);
    }

    for (int step=0; step<3; ++step) {
        agg_kernel<<<(NODES*64+255)/256,256>>>(base, G2, G3, sendc, offsets, agg);
        TDesc j = TD(agg, wPP + 256*NF_, 0, ppc, pe, pe, 0, NODES, 1, 1, NT_NODE64);
        tc64_multi<<<j.ntiles,256>>>(j,Z);
        if (step < 2) {
            TDesc c = TD(pe, wRP + 256*NF_, 0, 0,0, G2, 0, NODES, 0, 0, NT_NODE64);
            TDesc d = TD(pe, wRP + 512*NF_, 0, 0,0, G3, 0, NODES, 0, 0, NT_NODE64);
            tc64_multi<<<c.ntiles+d.ntiles,256>>>(c,d);
        }
    }

    // final: pr GEMM with fused 256->3 output epilogue
    {
        TDesc k = TD(pe, wPR0, pr_b0, 0,0, 0, 0, NODES, 1, 0, NT_NODE64);
        k.out_mode = 1; k.w1 = pr_w1; k.outp = out;
        tc64_multi<<<k.ntiles,256>>>(k,Z);
    }
}

// round 16
// speedup vs baseline: 1.3722x; 1.1823x over previous
#include <cuda_runtime.h>
#include <cuda_fp16.h>

#define B_    4
#define NH_   4
#define N_    1000
#define NF_   256
#define K_TOP 10
#define NODES (B_*N_)       // 4000
#define EDGES (B_*K_TOP*N_) // 40000

// ---- fp32 scratch ----
#define OFF_SCUR 0
#define OFF_ACUR (OFF_SCUR + NODES*3)
#define OFF_PEIN (OFF_ACUR + NODES)
#define OFF_FLAG (OFF_PEIN + NODES*16)
#define OFF_REIN (OFF_FLAG + EDGES)
#define OFF_BASE (OFF_REIN + EDGES*5)
#define OFF_G2   (OFF_BASE + EDGES*NF_)
#define OFF_G3   (OFF_G2   + NODES*NF_)
#define OFF_PPC  (OFF_G3   + NODES*NF_)
#define SCRATCH_TOTAL (OFF_PPC + NODES*NF_)

// ---- fp16 scratch (halves) ----
#define HOFF_PEH  0
#define HOFF_PE   (HOFF_PEH  + NODES*NF_)
#define HOFF_AGG  (HOFF_PE   + NODES*NF_)
#define HOFF_BUFA (HOFF_AGG  + NODES*NF_)
#define HOFF_BUFB (HOFF_BUFA + EDGES*NF_)
#define HOFF_W    (HOFF_BUFB + EDGES*NF_)
#define HTOTAL    (HOFF_W + 2304*NF_)
// weight sub-offsets (halves), k2-interleaved packing
#define HW_PE1  (HOFF_W + 0)
#define HW_RE1  (HOFF_W + 256*NF_)
#define HW_RE2  (HOFF_W + 512*NF_)
#define HW_RP   (HOFF_W + 768*NF_)      // 768 rows
#define HW_PP   (HOFF_W + 1536*NF_)     // 512 rows
#define HW_PR0  (HOFF_W + 2048*NF_)

__device__ float  g_scratch[SCRATCH_TOTAL];
__device__ __half g_half[HTOTAL];
__device__ int    g_send[EDGES];
__device__ int    g_sendc[EDGES];
__device__ int    g_offsets[NODES+1];
__device__ int    g_Mact[1];

// ---------------------------------------------------------------------------
// combo: topk (8-way split) + prep + wcvt(fp16, k2-interleaved) — one launch
// ---------------------------------------------------------------------------
#define COMBO_TOPK   128
#define COMBO_PREP   16
#define COMBO_WCVT   2304
#define COMBO_BLOCKS (COMBO_TOPK + COMBO_PREP + COMBO_WCVT)

__global__ void __launch_bounds__(256)
combo_kernel(const float* __restrict__ a_hist,
             const float* __restrict__ s_hist,
             const float* __restrict__ s_delta,
             const float* __restrict__ pr_b1,
             const float* __restrict__ pe_w1, const float* __restrict__ re_w1,
             const float* __restrict__ re_w2, const float* __restrict__ rp_w,
             const float* __restrict__ pp_w,  const float* __restrict__ pr_w0,
             float* __restrict__ S, __half* __restrict__ H,
             int* __restrict__ send, float* __restrict__ flag,
             float* __restrict__ out)
{
    int bid = blockIdx.x;
    int tid = threadIdx.x;

    if (bid < COMBO_TOPK) {
        __shared__ float sx[N_], sy[N_], sz[N_];
        __shared__ unsigned char st[N_];
        __shared__ float md[256][K_TOP];
        __shared__ short mi[256][K_TOP];
        int b = bid >> 5;
        int xb = bid & 31;
        for (int j = tid; j < N_; j += 256) {
            const float* sh = s_hist + ((size_t)(b*NH_ + NH_-1)*N_ + j)*3;
            sx[j]=sh[0]; sy[j]=sh[1]; sz[j]=sh[2];
            st[j] = a_hist[(b*NH_ + NH_-1)*N_ + j] > 0.5f ? 1 : 0;
        }
        __syncthreads();
        int li = tid & 31;
        int part = tid >> 5;
        int i = xb*32 + li;
        float dv[K_TOP]; short iv[K_TOP];
#pragma unroll
        for (int t=0;t<K_TOP;++t){ dv[t]=3.0e38f; iv[t]=0; }
        if (i < N_) {
            bool ti = st[i] != 0;
            float xi=sx[i], yi=sy[i], zi=sz[i];
            int j0 = part*125, j1 = j0+125;
            for (int j=j0;j<j1;++j) {
                float dx=__fadd_rn(xi,-sx[j]), dy=__fadd_rn(yi,-sy[j]), dz=__fadd_rn(zi,-sz[j]);
                float d = __fadd_rn(__fadd_rn(__fmul_rn(dx,dx),__fmul_rn(dy,dy)),__fmul_rn(dz,dz));
                if (ti && st[j]) d = 1e10f;
                if (d < dv[K_TOP-1]) {
#pragma unroll
                    for (int t=K_TOP-1; t>=1; --t) {
                        if (d < dv[t-1])      { dv[t]=dv[t-1]; iv[t]=iv[t-1]; }
                        else if (d < dv[t])   { dv[t]=d;       iv[t]=(short)j; }
                    }
                    if (d < dv[0]) { dv[0]=d; iv[0]=(short)j; }
                }
            }
        }
#pragma unroll
        for (int t=0;t<K_TOP;++t){ md[tid][t]=dv[t]; mi[tid][t]=iv[t]; }
        __syncthreads();
        if (part == 0 && i < N_) {
            bool ti = st[i] != 0;
            int ptr[8] = {0,0,0,0,0,0,0,0};
            int gi = b*N_ + i;
#pragma unroll
            for (int t=0;t<K_TOP;++t) {
                float best = 3.5e38f; int bp = 0;
#pragma unroll
                for (int p=0;p<8;++p) {
                    float dd = md[li + p*32][ptr[p]];
                    if (dd < best) { best = dd; bp = p; }
                }
                int j = mi[li + bp*32][ptr[bp]];
                ptr[bp]++;
                int rg = gi*K_TOP + t;
                send[rg] = b*N_ + j;
                flag[rg] = (!ti && best < 0.25f) ? 1.0f : 0.0f;
            }
        }
    } else if (bid < COMBO_TOPK + COMBO_PREP) {
        int idx = (bid - COMBO_TOPK)*256 + tid;
        if (idx >= NODES) return;
        int b = idx / N_, n = idx % N_;
        float* scur = S + OFF_SCUR;
        float* acur = S + OFF_ACUR;
        float* pein = S + OFF_PEIN;
        acur[idx] = a_hist[(b*NH_ + NH_-1)*N_ + n];
        const float* sh = s_hist + ((size_t)(b*NH_ + NH_-1)*N_ + n)*3;
        float s0=sh[0], s1=sh[1], s2=sh[2];
        scur[idx*3+0]=s0; scur[idx*3+1]=s1; scur[idx*3+2]=s2;
        out[idx*3+0] = s0 + pr_b1[0];
        out[idx*3+1] = s1 + pr_b1[1];
        out[idx*3+2] = s2 + pr_b1[2];
        float* pp = pein + (size_t)idx*16;
#pragma unroll
        for (int h=0; h<NH_; ++h) {
            const float* sd = s_delta + ((size_t)(b*NH_+h)*N_ + n)*3;
            pp[h*3+0]=sd[0]; pp[h*3+1]=sd[1]; pp[h*3+2]=sd[2];
            pp[12+h] = a_hist[(b*NH_+h)*N_ + n];
        }
    } else {
        // wcvt: fp32 -> fp16, k2-interleaved: dst[(k>>1)*512 + c*2 + (k&1)]
        int i = (bid - COMBO_TOPK - COMBO_PREP)*256 + tid;
        const float* src; __half* dst;
        int idx = i;
        if (idx < 256*NF_)        { src = pe_w1;  dst = H + HW_PE1; }
        else if (idx < 512*NF_)   { src = re_w1;  dst = H + HW_RE1; idx -= 256*NF_; }
        else if (idx < 768*NF_)   { src = re_w2;  dst = H + HW_RE2; idx -= 512*NF_; }
        else if (idx < 1536*NF_)  { src = rp_w;   dst = H + HW_RP;  idx -= 768*NF_; }
        else if (idx < 2048*NF_)  { src = pp_w;   dst = H + HW_PP;  idx -= 1536*NF_; }
        else                      { src = pr_w0;  dst = H + HW_PR0; idx -= 2048*NF_; }
        int k = idx >> 8, c = idx & 255;
        dst[(k>>1)*512 + c*2 + (k&1)] = __float2half_rn(src[idx]);
    }
}

// ---------------------------------------------------------------------------
__global__ void __launch_bounds__(1024)
scan_kernel(const float* __restrict__ flag, int* __restrict__ offsets,
            int* __restrict__ Mact)
{
    __shared__ int wsum[32];
    int tid = threadIdx.x;
    int lane = tid & 31, wrp = tid >> 5;

    float v[40];
    if (tid < 1000) {
        const float4* f4 = (const float4*)(flag + tid*40);
#pragma unroll
        for (int i=0;i<10;++i) {
            float4 t = f4[i];
            v[i*4+0]=t.x; v[i*4+1]=t.y; v[i*4+2]=t.z; v[i*4+3]=t.w;
        }
    } else {
#pragma unroll
        for (int i=0;i<40;++i) v[i]=0.f;
    }
    int local[4];
    int run = 0;
#pragma unroll
    for (int q=0;q<4;++q) {
        int c = 0;
#pragma unroll
        for (int k=0;k<K_TOP;++k) c += (v[q*10+k] != 0.f);
        local[q]=run; run += c;
    }
    int inc = run;
#pragma unroll
    for (int d=1; d<32; d<<=1) {
        int t = __shfl_up_sync(0xffffffffu, inc, d);
        if (lane >= d) inc += t;
    }
    if (lane == 31) wsum[wrp] = inc;
    __syncthreads();
    if (wrp == 0) {
        int w = wsum[lane];
#pragma unroll
        for (int d=1; d<32; d<<=1) {
            int t = __shfl_up_sync(0xffffffffu, w, d);
            if (lane >= d) w += t;
        }
        wsum[lane] = w;
    }
    __syncthreads();
    int before = inc - run + (wrp ? wsum[wrp-1] : 0);
#pragma unroll
    for (int q=0;q<4;++q) {
        int node = tid*4+q;
        if (node < NODES) offsets[node] = before + local[q];
    }
    if (tid == 1023) { int tot = wsum[31]; offsets[NODES] = tot; Mact[0] = tot; }
}

// ---------------------------------------------------------------------------
__global__ void fill_kernel(const float* __restrict__ scur, const float* __restrict__ acur,
                            const int* __restrict__ send, const float* __restrict__ flag,
                            const int* __restrict__ offsets,
                            int* __restrict__ sendc, float* __restrict__ rein)
{
    int r = blockIdx.x*blockDim.x+threadIdx.x;
    if (r >= EDGES) return;
    if (flag[r] == 0.f) return;
    int node = r / K_TOP, k = r % K_TOP;
    int rank = 0;
    for (int kk = 0; kk < k; ++kk) rank += (flag[node*K_TOP+kk] != 0.f);
    int pos = offsets[node] + rank;
    int s = send[r];
    sendc[pos] = s;
    float* o = rein + (size_t)pos*5;
    o[0] = acur[node];
    o[1] = acur[s];
    o[2] = scur[node*3+0] - scur[s*3+0];
    o[3] = scur[node*3+1] - scur[s*3+1];
    o[4] = scur[node*3+2] - scur[s*3+2];
}

// ---------------------------------------------------------------------------
// direct small-K GEMM: 32 rows/block, fp16 output
// ---------------------------------------------------------------------------
struct GDesc {
    const float* A; const float* W; const float* bias; __half* C;
    const int* Mp; int Mconst; int K; int ntiles;
};

__global__ void __launch_bounds__(256)
smallk_multi(GDesc d0, GDesc d1)
{
    int bx = blockIdx.x;
    GDesc d;
    if (bx < d0.ntiles) d = d0;
    else { bx -= d0.ntiles; d = d1; }

    int M = d.Mp ? __ldg(d.Mp) : d.Mconst;
    int bm = bx * 32;
    if (bm >= M) return;
    int K = d.K;

    __shared__ float Ws[16][NF_];
    __shared__ float Asm[32][17];
    int tid = threadIdx.x;

    for (int i = tid; i < K*NF_; i += 256) Ws[i>>8][i&255] = d.W[i];
    int rows = M - bm; if (rows > 32) rows = 32;
    for (int i = tid; i < rows*K; i += 256) {
        int r = i / K, k = i % K;
        Asm[r][k] = d.A[(size_t)(bm+r)*K + k];
    }
    __syncthreads();

    float b = d.bias[tid];
    if (K == 16) {
        for (int r = 0; r < rows; ++r) {
            float acc = b;
#pragma unroll
            for (int k = 0; k < 16; ++k) acc = fmaf(Asm[r][k], Ws[k][tid], acc);
            d.C[(size_t)(bm+r)*NF_ + tid] = __float2half_rn(fmaxf(acc, 0.f));
        }
    } else {  // K == 5
        for (int r = 0; r < rows; ++r) {
            float acc = b;
#pragma unroll
            for (int k = 0; k < 5; ++k) acc = fmaf(Asm[r][k], Ws[k][tid], acc);
            d.C[(size_t)(bm+r)*NF_ + tid] = __float2half_rn(fmaxf(acc, 0.f));
        }
    }
}

// ---------------------------------------------------------------------------
struct TDesc {
    const __half* A; const __half* W; const float* bias;
    const float* add0; const __half* add1; void* C;
    const int* Mp; int Mconst; int relu; int out_mode; int rt;
    const float* w1; float* outp; int ntiles;
};

#define SA2 40    // A smem stride (halves): words r*20+tig conflict-free
#define SB2 272   // B smem stride (halves): 136 words == 8 mod 32 -> conflict-free

// ---------------------------------------------------------------------------
// fp16 tc GEMM, 128x128 tiles, m16n8k16, software-pipelined
// ---------------------------------------------------------------------------
__global__ void __launch_bounds__(256, 2)
tc_multi(TDesc d0, TDesc d1, TDesc d2, TDesc d3)
{
    int bx = blockIdx.x;
    TDesc d;
    if (bx < d0.ntiles) d = d0;
    else { bx -= d0.ntiles;
        if (bx < d1.ntiles) d = d1;
        else { bx -= d1.ntiles;
            if (bx < d2.ntiles) d = d2;
            else { bx -= d2.ntiles; d = d3; } } }

    int M = d.Mp ? __ldg(d.Mp) : d.Mconst;
    int bm = (bx >> 1) * 128;
    if (bm >= M) return;
    int bn = (bx & 1) * 128;
    const __half* A = d.A;
    const __half* W = d.W;

    __shared__ __align__(16) __half As[2][128*SA2];
    __shared__ __align__(16) __half Bs[2][8*SB2];

    int tid = threadIdx.x;
    int wid = tid >> 5, lane = tid & 31;
    int gid = lane >> 2, tig = lane & 3;
    int warp_m = (wid & 3) * 32;
    int warp_n = (wid >> 2) * 64;

    // load coords: A 2048 halves: row=tid>>1, kq=(tid&1)*8 ; B 2048 halves: k2=tid>>5, c8=(tid&31)*8
    int a_row = tid >> 1, a_kq = (tid & 1) * 8;
    int b_k2 = tid >> 5,  b_c8 = (tid & 31) * 8;

    uint4 ar, br;

#define TCP_LDG(k0)                                                           \
    {                                                                         \
        int gm = bm + a_row;                                                  \
        ar = make_uint4(0,0,0,0);                                             \
        if (gm < M) ar = *(const uint4*)(A + (size_t)gm * NF_ + (k0) + a_kq); \
        br = *(const uint4*)(W + (size_t)(((k0)>>1) + b_k2) * 512 + bn*2 + b_c8);\
    }

#define TCP_STS(buf)                                                          \
    {                                                                         \
        *(uint4*)&As[buf][a_row*SA2 + a_kq] = ar;                             \
        *(uint4*)&Bs[buf][b_k2*SB2 + b_c8] = br;                              \
    }

    float acc[2][8][4];
#pragma unroll
    for (int f=0;f<2;++f)
#pragma unroll
        for (int g=0;g<8;++g)
#pragma unroll
            for (int q=0;q<4;++q) acc[f][g][q]=0.f;

    TCP_LDG(0);
    TCP_STS(0);
    __syncthreads();

#pragma unroll 1
    for (int t = 0; t < 16; ++t) {
        int cur = t & 1, nxt = cur ^ 1;
        if (t + 1 < 16) TCP_LDG((t + 1) * 16);
        {
            unsigned a[2][4], bfr[8][2];
#pragma unroll
            for (int f = 0; f < 2; ++f) {
                int r0 = warp_m + f*16 + gid;
                a[f][0] = *(const unsigned*)&As[cur][r0*SA2 + 2*tig];
                a[f][1] = *(const unsigned*)&As[cur][(r0+8)*SA2 + 2*tig];
                a[f][2] = *(const unsigned*)&As[cur][r0*SA2 + 2*tig + 8];
                a[f][3] = *(const unsigned*)&As[cur][(r0+8)*SA2 + 2*tig + 8];
            }
#pragma unroll
            for (int g = 0; g < 8; ++g) {
                int col = warp_n + g*8 + gid;
                bfr[g][0] = *(const unsigned*)&Bs[cur][tig*SB2 + col*2];
                bfr[g][1] = *(const unsigned*)&Bs[cur][(tig+4)*SB2 + col*2];
            }
#pragma unroll
            for (int f = 0; f < 2; ++f)
#pragma unroll
                for (int g = 0; g < 8; ++g) {
                    asm volatile(
                        "mma.sync.aligned.m16n8k16.row.col.f32.f16.f16.f32 "
                        "{%0,%1,%2,%3},{%4,%5,%6,%7},{%8,%9},{%0,%1,%2,%3};"
                        : "+f"(acc[f][g][0]), "+f"(acc[f][g][1]),
                          "+f"(acc[f][g][2]), "+f"(acc[f][g][3])
                        : "r"(a[f][0]), "r"(a[f][1]), "r"(a[f][2]), "r"(a[f][3]),
                          "r"(bfr[g][0]), "r"(bfr[g][1]));
                }
        }
        if (t + 1 < 16) TCP_STS(nxt);
        __syncthreads();
    }
#undef TCP_LDG
#undef TCP_STS

#pragma unroll
    for (int f = 0; f < 2; ++f) {
        int r0 = bm + warp_m + f*16 + gid;
        int r1 = r0 + 8;
#pragma unroll
        for (int g = 0; g < 8; ++g) {
            int ccol = bn + warp_n + g*8 + tig*2;
            float b0 = d.bias ? d.bias[ccol] : 0.f;
            float b1 = d.bias ? d.bias[ccol+1] : 0.f;
#pragma unroll
            for (int h = 0; h < 2; ++h) {
                int r = h ? r1 : r0;
                if (r >= M) continue;
                size_t off = (size_t)r * NF_ + ccol;
                float v0 = acc[f][g][2*h+0] + b0;
                float v1 = acc[f][g][2*h+1] + b1;
                if (d.add0) { v0 += d.add0[off]; v1 += d.add0[off+1]; }
                if (d.add1) { v0 += __half2float(d.add1[off]); v1 += __half2float(d.add1[off+1]); }
                if (d.relu) { v0 = fmaxf(v0,0.f); v1 = fmaxf(v1,0.f); }
                if (d.rt)   { *(__half2*)((__half*)d.C + off) = __floats2half2_rn(v0, v1); }
                else        { *(float2*)((float*)d.C + off) = make_float2(v0, v1); }
            }
        }
    }
}

// ---------------------------------------------------------------------------
// fp16 tc GEMM, 64x128 tiles, m16n8k16, software-pipelined
// ---------------------------------------------------------------------------
__global__ void __launch_bounds__(256, 2)
tc64_multi(TDesc d0, TDesc d1)
{
    int bx = blockIdx.x;
    TDesc d;
    if (bx < d0.ntiles) d = d0;
    else { bx -= d0.ntiles; d = d1; }

    int M = d.Mconst;
    int bm = (bx >> 1) * 64;
    if (bm >= M) return;
    int bn = (bx & 1) * 128;
    const __half* A = d.A;
    const __half* W = d.W;

    __shared__ __align__(16) __half As[2][64*SA2];
    __shared__ __align__(16) __half Bs[2][8*SB2];

    int tid = threadIdx.x;
    int wid = tid >> 5, lane = tid & 31;
    int gid = lane >> 2, tig = lane & 3;
    int warp_m = (wid & 1) * 32;
    int warp_n = (wid >> 1) * 32;

    int a_row = tid >> 2, a_kq = (tid & 3) * 4;   // 64 rows x 16 halves, 4 halves/thread
    int b_k2 = tid >> 5,  b_c8 = (tid & 31) * 8;

    uint2 ar; uint4 br;

#define TCP64_LDG(k0)                                                         \
    {                                                                         \
        int gm = bm + a_row;                                                  \
        ar = make_uint2(0,0);                                                 \
        if (gm < M) ar = *(const uint2*)(A + (size_t)gm * NF_ + (k0) + a_kq); \
        br = *(const uint4*)(W + (size_t)(((k0)>>1) + b_k2) * 512 + bn*2 + b_c8);\
    }

#define TCP64_STS(buf)                                                        \
    {                                                                         \
        *(uint2*)&As[buf][a_row*SA2 + a_kq] = ar;                             \
        *(uint4*)&Bs[buf][b_k2*SB2 + b_c8] = br;                              \
    }

    float acc[2][4][4];
#pragma unroll
    for (int f=0;f<2;++f)
#pragma unroll
        for (int g=0;g<4;++g)
#pragma unroll
            for (int q=0;q<4;++q) acc[f][g][q]=0.f;

    TCP64_LDG(0);
    TCP64_STS(0);
    __syncthreads();

#pragma unroll 1
    for (int t = 0; t < 16; ++t) {
        int cur = t & 1, nxt = cur ^ 1;
        if (t + 1 < 16) TCP64_LDG((t + 1) * 16);
        {
            unsigned a[2][4], bfr[4][2];
#pragma unroll
            for (int f = 0; f < 2; ++f) {
                int r0 = warp_m + f*16 + gid;
                a[f][0] = *(const unsigned*)&As[cur][r0*SA2 + 2*tig];
                a[f][1] = *(const unsigned*)&As[cur][(r0+8)*SA2 + 2*tig];
                a[f][2] = *(const unsigned*)&As[cur][r0*SA2 + 2*tig + 8];
                a[f][3] = *(const unsigned*)&As[cur][(r0+8)*SA2 + 2*tig + 8];
            }
#pragma unroll
            for (int g = 0; g < 4; ++g) {
                int col = warp_n + g*8 + gid;
                bfr[g][0] = *(const unsigned*)&Bs[cur][tig*SB2 + col*2];
                bfr[g][1] = *(const unsigned*)&Bs[cur][(tig+4)*SB2 + col*2];
            }
#pragma unroll
            for (int f = 0; f < 2; ++f)
#pragma unroll
                for (int g = 0; g < 4; ++g) {
                    asm volatile(
                        "mma.sync.aligned.m16n8k16.row.col.f32.f16.f16.f32 "
                        "{%0,%1,%2,%3},{%4,%5,%6,%7},{%8,%9},{%0,%1,%2,%3};"
                        : "+f"(acc[f][g][0]), "+f"(acc[f][g][1]),
                          "+f"(acc[f][g][2]), "+f"(acc[f][g][3])
                        : "r"(a[f][0]), "r"(a[f][1]), "r"(a[f][2]), "r"(a[f][3]),
                          "r"(bfr[g][0]), "r"(bfr[g][1]));
                }
        }
        if (t + 1 < 16) TCP64_STS(nxt);
        __syncthreads();
    }
#undef TCP64_LDG
#undef TCP64_STS

    if (!d.out_mode) {
#pragma unroll
        for (int f = 0; f < 2; ++f) {
            int r0 = bm + warp_m + f*16 + gid;
            int r1 = r0 + 8;
#pragma unroll
            for (int g = 0; g < 4; ++g) {
                int ccol = bn + warp_n + g*8 + tig*2;
                float b0 = d.bias ? d.bias[ccol] : 0.f;
                float b1 = d.bias ? d.bias[ccol+1] : 0.f;
#pragma unroll
                for (int h = 0; h < 2; ++h) {
                    int r = h ? r1 : r0;
                    if (r >= M) continue;
                    size_t off = (size_t)r * NF_ + ccol;
                    float v0 = acc[f][g][2*h+0] + b0;
                    float v1 = acc[f][g][2*h+1] + b1;
                    if (d.add0) { v0 += d.add0[off]; v1 += d.add0[off+1]; }
                    if (d.add1) { v0 += __half2float(d.add1[off]); v1 += __half2float(d.add1[off+1]); }
                    if (d.relu) { v0 = fmaxf(v0,0.f); v1 = fmaxf(v1,0.f); }
                    if (d.rt)   { *(__half2*)((__half*)d.C + off) = __floats2half2_rn(v0, v1); }
                    else        { *(float2*)((float*)d.C + off) = make_float2(v0, v1); }
                }
            }
        }
    } else {
        // hout = relu(acc + bias); out[row] += hout-slice @ w1 (256x3)
#pragma unroll
        for (int f = 0; f < 2; ++f) {
            int r0 = bm + warp_m + f*16 + gid;
            int r1 = r0 + 8;
            float p0[3] = {0.f,0.f,0.f};
            float p1[3] = {0.f,0.f,0.f};
#pragma unroll
            for (int g = 0; g < 4; ++g) {
                int ccol = bn + warp_n + g*8 + tig*2;
#pragma unroll
                for (int c = 0; c < 2; ++c) {
                    int col = ccol + c;
                    float w0 = __ldg(d.w1 + col*3 + 0);
                    float wv = __ldg(d.w1 + col*3 + 1);
                    float w2 = __ldg(d.w1 + col*3 + 2);
                    float bb = d.bias[col];
                    float v0 = fmaxf(acc[f][g][0+c] + bb, 0.f);
                    float v1 = fmaxf(acc[f][g][2+c] + bb, 0.f);
                    p0[0]=fmaf(v0,w0,p0[0]); p0[1]=fmaf(v0,wv,p0[1]); p0[2]=fmaf(v0,w2,p0[2]);
                    p1[0]=fmaf(v1,w0,p1[0]); p1[1]=fmaf(v1,wv,p1[1]); p1[2]=fmaf(v1,w2,p1[2]);
                }
            }
#pragma unroll
            for (int j = 0; j < 3; ++j) {
                p0[j] += __shfl_xor_sync(0xffffffffu, p0[j], 1);
                p0[j] += __shfl_xor_sync(0xffffffffu, p0[j], 2);
                p1[j] += __shfl_xor_sync(0xffffffffu, p1[j], 1);
                p1[j] += __shfl_xor_sync(0xffffffffu, p1[j], 2);
            }
            if (tig == 0) {
                if (r0 < M) {
                    atomicAdd(d.outp + r0*3 + 0, p0[0]);
                    atomicAdd(d.outp + r0*3 + 1, p0[1]);
                    atomicAdd(d.outp + r0*3 + 2, p0[2]);
                }
                if (r1 < M) {
                    atomicAdd(d.outp + r1*3 + 0, p1[0]);
                    atomicAdd(d.outp + r1*3 + 1, p1[1]);
                    atomicAdd(d.outp + r1*3 + 2, p1[2]);
                }
            }
        }
    }
}

// ---------------------------------------------------------------------------
// agg: fp32 inputs (base/G2/G3), fp16 output
// ---------------------------------------------------------------------------
__global__ void agg_kernel(const float* __restrict__ base, const float* __restrict__ G2,
                           const float* __restrict__ G3,
                           const int* __restrict__ sendc, const int* __restrict__ offsets,
                           __half* __restrict__ agg)
{
    int w = blockIdx.x*blockDim.x + threadIdx.x;
    if (w >= NODES*64) return;
    int node = w >> 6, q = (w & 63) * 4;
    float4 g2 = *(const float4*)(G2 + (size_t)node*NF_ + q);
    int e0 = offsets[node], e1 = offsets[node+1];
    float4 a = make_float4(0.f,0.f,0.f,0.f);
    for (int e = e0; e < e1; ++e) {
        float4 bs = *(const float4*)(base + (size_t)e*NF_ + q);
        float4 g3 = *(const float4*)(G3 + (size_t)sendc[e]*NF_ + q);
        a.x += fmaxf(bs.x + g2.x + g3.x, 0.f);
        a.y += fmaxf(bs.y + g2.y + g3.y, 0.f);
        a.z += fmaxf(bs.z + g2.z + g3.z, 0.f);
        a.w += fmaxf(bs.w + g2.w + g3.w, 0.f);
    }
    __half2 h0 = __floats2half2_rn(a.x, a.y);
    __half2 h1 = __floats2half2_rn(a.z, a.w);
    *(__half2*)(agg + (size_t)node*NF_ + q)     = h0;
    *(__half2*)(agg + (size_t)node*NF_ + q + 2) = h1;
}

// ---------------------------------------------------------------------------
extern "C" void kernel_launch(void* const* d_in, const int* in_sizes, int n_in,
                              void* d_out, int out_size)
{
    const float* a_hist =(const float*)d_in[0];
    const float* s_hist =(const float*)d_in[1];
    const float* s_delta=(const float*)d_in[2];
    const float* pe_w0=(const float*)d_in[3];  const float* pe_b0=(const float*)d_in[4];
    const float* pe_w1=(const float*)d_in[5];  const float* pe_b1=(const float*)d_in[6];
    const float* re_w0=(const float*)d_in[7];  const float* re_b0=(const float*)d_in[8];
    const float* re_w1=(const float*)d_in[9];  const float* re_b1=(const float*)d_in[10];
    const float* re_w2=(const float*)d_in[11]; const float* re_b2=(const float*)d_in[12];
    const float* rp_w =(const float*)d_in[13]; const float* rp_b =(const float*)d_in[14];
    const float* pp_w =(const float*)d_in[15]; const float* pp_b =(const float*)d_in[16];
    const float* pr_w0=(const float*)d_in[17]; const float* pr_b0=(const float*)d_in[18];
    const float* pr_w1=(const float*)d_in[19]; const float* pr_b1=(const float*)d_in[20];
    float* out = (float*)d_out;

    void* sp;   cudaGetSymbolAddress(&sp, g_scratch);
    void* hp;   cudaGetSymbolAddress(&hp, g_half);
    void* p1;   cudaGetSymbolAddress(&p1, g_send);
    void* p2;   cudaGetSymbolAddress(&p2, g_sendc);
    void* p3;   cudaGetSymbolAddress(&p3, g_offsets);
    void* p4;   cudaGetSymbolAddress(&p4, g_Mact);
    float*  S = (float*)sp;
    __half* H = (__half*)hp;
    int* send    = (int*)p1;
    int* sendc   = (int*)p2;
    int* offsets = (int*)p3;
    int* Mact    = (int*)p4;

    float* scur=S+OFF_SCUR; float* acur=S+OFF_ACUR; float* pein=S+OFF_PEIN;
    float* flag=S+OFF_FLAG; float* rein=S+OFF_REIN; float* base=S+OFF_BASE;
    float* G2  =S+OFF_G2;   float* G3  =S+OFF_G3;   float* ppc =S+OFF_PPC;
    __half* peh =H+HOFF_PEH;  __half* pe  =H+HOFF_PE;   __half* agg =H+HOFF_AGG;
    __half* bufA=H+HOFF_BUFA; __half* bufB=H+HOFF_BUFB;
    __half* wPE1=H+HW_PE1; __half* wRE1=H+HW_RE1; __half* wRE2=H+HW_RE2;
    __half* wRP =H+HW_RP;  __half* wPP =H+HW_PP;  __half* wPR0=H+HW_PR0;

    const int NT_NODE   = ((NODES+127)/128)*2;  // 64
    const int NT_NODE64 = ((NODES+63)/64)*2;    // 126
    const int NT_EDGE   = ((EDGES+127)/128)*2;  // 626 worst case

    TDesc Z = {};

    auto TD = [&](const __half* A,const __half* W,const float* bias,
                  const float* a0,const __half* a1,void* C,
                  const int* Mp,int Mc,int relu,int rt,int nt)->TDesc {
        TDesc d; d.A=A; d.W=W; d.bias=bias; d.add0=a0; d.add1=a1; d.C=C;
        d.Mp=Mp; d.Mconst=Mc; d.relu=relu; d.out_mode=0; d.rt=rt;
        d.w1=0; d.outp=0; d.ntiles=nt;
        return d;
    };

    // combo: topk + prep + wcvt (all input-only)
    combo_kernel<<<COMBO_BLOCKS,256>>>(a_hist,s_hist,s_delta,pr_b1,
                                       pe_w1,re_w1,re_w2,rp_w,pp_w,pr_w0,
                                       S, H, send, flag, out);
    scan_kernel<<<1,1024>>>(flag, offsets, Mact);
    fill_kernel<<<(EDGES+255)/256,256>>>(scur,acur,send,flag,offsets,sendc,rein);

    // L1: peh (K=16, node) + bufA (K=5, edges) — 32 rows/block, fp16 out
    {
        GDesc dA; dA.A=pein; dA.W=pe_w0; dA.bias=pe_b0; dA.C=peh;
        dA.Mp=0; dA.Mconst=NODES; dA.K=16; dA.ntiles=(NODES+31)/32;
        GDesc dB; dB.A=rein; dB.W=re_w0; dB.bias=re_b0; dB.C=bufA;
        dB.Mp=Mact; dB.Mconst=0; dB.K=5; dB.ntiles=(EDGES+31)/32;
        smallk_multi<<<dA.ntiles+dB.ntiles,256>>>(dA,dB);
    }
    // L2: pe = relu(peh@wPE1+b) [h]  +  bufB = relu(bufA@wRE1+b) [h]
    {
        TDesc a = TD(peh, wPE1, pe_b1, 0,0, pe,  0, NODES, 1, 1, NT_NODE);
        TDesc b = TD(bufA, wRE1, re_b1, 0,0, bufB, Mact, 0, 1, 1, NT_EDGE);
        tc_multi<<<a.ntiles+b.ntiles,256>>>(a,b,Z,Z);
    }
    // L3: ppc (f32) + renc [h] + G2_0 + G3_0 (f32)
    {
        TDesc a = TD(pe,   wPP,  pp_b,  0,0, ppc,  0, NODES, 0, 0, NT_NODE);
        TDesc b = TD(bufB, wRE2, re_b2, 0,0, bufA, Mact, 0, 1, 1, NT_EDGE);
        TDesc c = TD(pe, wRP + 256*NF_, 0, 0,0, G2, 0, NODES, 0, 0, NT_NODE);
        TDesc d = TD(pe, wRP + 512*NF_, 0, 0,0, G3, 0, NODES, 0, 0, NT_NODE);
        tc_multi<<<a.ntiles+b.ntiles+c.ntiles+d.ntiles,256>>>(a,b,c,d);
    }
    // L4: base = renc @ wRP[0:256] + rp_b  (f32)
    {
        TDesc a = TD(bufA, wRP, rp_b, 0,0, base, Mact, 0, 0, 0, NT_EDGE);
        tc_multi<<<a.ntiles,256>>>(a,Z,Z,Z);
    }

    for (int step=0; step<3; ++step) {
        agg_kernel<<<(NODES*64+255)/256,256>>>(base, G2, G3, sendc, offsets, agg);
        // J: pe = relu(ppc + agg@wPP[256:] + pe) [h]
        TDesc j = TD(agg, wPP + 256*NF_, 0, ppc, pe, pe, 0, NODES, 1, 1, NT_NODE64);
        tc64_multi<<<j.ntiles,256>>>(j,Z);
        if (step < 2) {
            TDesc c = TD(pe, wRP + 256*NF_, 0, 0,0, G2, 0, NODES, 0, 0, NT_NODE64);
            TDesc d = TD(pe, wRP + 512*NF_, 0, 0,0, G3, 0, NODES, 0, 0, NT_NODE64);
            tc64_multi<<<c.ntiles+d.ntiles,256>>>(c,d);
        }
    }

    // final: pr GEMM with fused 256->3 output epilogue
    {
        TDesc k = TD(pe, wPR0, pr_b0, 0,0, 0, 0, NODES, 1, 0, NT_NODE64);
        k.out_mode = 1; k.w1 = pr_w1; k.outp = out;
        tc64_multi<<<k.ntiles,256>>>(k,Z);
    }
}

// round 17
// speedup vs baseline: 1.3853x; 1.0095x over previous
#include <cuda_runtime.h>
#include <cuda_fp16.h>

#define B_    4
#define NH_   4
#define N_    1000
#define NF_   256
#define K_TOP 10
#define NODES (B_*N_)       // 4000
#define EDGES (B_*K_TOP*N_) // 40000

// ---- fp32 scratch ----
#define OFF_SCUR 0
#define OFF_ACUR (OFF_SCUR + NODES*3)
#define OFF_PEIN (OFF_ACUR + NODES)
#define OFF_FLAG (OFF_PEIN + NODES*16)
#define OFF_REIN (OFF_FLAG + EDGES)
#define OFF_PPC  (OFF_REIN + EDGES*5)
#define SCRATCH_TOTAL (OFF_PPC + NODES*NF_)

// ---- fp16 scratch (halves) ----
#define HOFF_PEH  0
#define HOFF_PE   (HOFF_PEH  + NODES*NF_)
#define HOFF_AGG  (HOFF_PE   + NODES*NF_)
#define HOFF_G2   (HOFF_AGG  + NODES*NF_)
#define HOFF_G3   (HOFF_G2   + NODES*NF_)
#define HOFF_BUFA (HOFF_G3   + NODES*NF_)
#define HOFF_BUFB (HOFF_BUFA + EDGES*NF_)
#define HOFF_BASE (HOFF_BUFB + EDGES*NF_)
#define HOFF_W    (HOFF_BASE + EDGES*NF_)
#define HTOTAL    (HOFF_W + 2304*NF_)
// weight sub-offsets (halves), k2-interleaved packing
#define HW_PE1  (HOFF_W + 0)
#define HW_RE1  (HOFF_W + 256*NF_)
#define HW_RE2  (HOFF_W + 512*NF_)
#define HW_RP   (HOFF_W + 768*NF_)      // 768 rows
#define HW_PP   (HOFF_W + 1536*NF_)     // 512 rows
#define HW_PR0  (HOFF_W + 2048*NF_)

__device__ float  g_scratch[SCRATCH_TOTAL];
__device__ __half g_half[HTOTAL];
__device__ int    g_send[EDGES];
__device__ int    g_sendc[EDGES];
__device__ int    g_offsets[NODES+1];
__device__ int    g_Mact[1];

// ---------------------------------------------------------------------------
// combo: topk (8-way split) + prep + wcvt(fp16, k2-interleaved) — one launch
// ---------------------------------------------------------------------------
#define COMBO_TOPK   128
#define COMBO_PREP   16
#define COMBO_WCVT   2304
#define COMBO_BLOCKS (COMBO_TOPK + COMBO_PREP + COMBO_WCVT)

__global__ void __launch_bounds__(256)
combo_kernel(const float* __restrict__ a_hist,
             const float* __restrict__ s_hist,
             const float* __restrict__ s_delta,
             const float* __restrict__ pr_b1,
             const float* __restrict__ pe_w1, const float* __restrict__ re_w1,
             const float* __restrict__ re_w2, const float* __restrict__ rp_w,
             const float* __restrict__ pp_w,  const float* __restrict__ pr_w0,
             float* __restrict__ S, __half* __restrict__ H,
             int* __restrict__ send, float* __restrict__ flag,
             float* __restrict__ out)
{
    int bid = blockIdx.x;
    int tid = threadIdx.x;

    if (bid < COMBO_TOPK) {
        __shared__ float sx[N_], sy[N_], sz[N_];
        __shared__ unsigned char st[N_];
        __shared__ float md[256][K_TOP];
        __shared__ short mi[256][K_TOP];
        int b = bid >> 5;
        int xb = bid & 31;
        for (int j = tid; j < N_; j += 256) {
            const float* sh = s_hist + ((size_t)(b*NH_ + NH_-1)*N_ + j)*3;
            sx[j]=sh[0]; sy[j]=sh[1]; sz[j]=sh[2];
            st[j] = a_hist[(b*NH_ + NH_-1)*N_ + j] > 0.5f ? 1 : 0;
        }
        __syncthreads();
        int li = tid & 31;
        int part = tid >> 5;
        int i = xb*32 + li;
        float dv[K_TOP]; short iv[K_TOP];
#pragma unroll
        for (int t=0;t<K_TOP;++t){ dv[t]=3.0e38f; iv[t]=0; }
        if (i < N_) {
            bool ti = st[i] != 0;
            float xi=sx[i], yi=sy[i], zi=sz[i];
            int j0 = part*125, j1 = j0+125;
            for (int j=j0;j<j1;++j) {
                float dx=__fadd_rn(xi,-sx[j]), dy=__fadd_rn(yi,-sy[j]), dz=__fadd_rn(zi,-sz[j]);
                float d = __fadd_rn(__fadd_rn(__fmul_rn(dx,dx),__fmul_rn(dy,dy)),__fmul_rn(dz,dz));
                if (ti && st[j]) d = 1e10f;
                if (d < dv[K_TOP-1]) {
#pragma unroll
                    for (int t=K_TOP-1; t>=1; --t) {
                        if (d < dv[t-1])      { dv[t]=dv[t-1]; iv[t]=iv[t-1]; }
                        else if (d < dv[t])   { dv[t]=d;       iv[t]=(short)j; }
                    }
                    if (d < dv[0]) { dv[0]=d; iv[0]=(short)j; }
                }
            }
        }
#pragma unroll
        for (int t=0;t<K_TOP;++t){ md[tid][t]=dv[t]; mi[tid][t]=iv[t]; }
        __syncthreads();
        if (part == 0 && i < N_) {
            bool ti = st[i] != 0;
            int ptr[8] = {0,0,0,0,0,0,0,0};
            int gi = b*N_ + i;
#pragma unroll
            for (int t=0;t<K_TOP;++t) {
                float best = 3.5e38f; int bp = 0;
#pragma unroll
                for (int p=0;p<8;++p) {
                    float dd = md[li + p*32][ptr[p]];
                    if (dd < best) { best = dd; bp = p; }
                }
                int j = mi[li + bp*32][ptr[bp]];
                ptr[bp]++;
                int rg = gi*K_TOP + t;
                send[rg] = b*N_ + j;
                flag[rg] = (!ti && best < 0.25f) ? 1.0f : 0.0f;
            }
        }
    } else if (bid < COMBO_TOPK + COMBO_PREP) {
        int idx = (bid - COMBO_TOPK)*256 + tid;
        if (idx >= NODES) return;
        int b = idx / N_, n = idx % N_;
        float* scur = S + OFF_SCUR;
        float* acur = S + OFF_ACUR;
        float* pein = S + OFF_PEIN;
        acur[idx] = a_hist[(b*NH_ + NH_-1)*N_ + n];
        const float* sh = s_hist + ((size_t)(b*NH_ + NH_-1)*N_ + n)*3;
        float s0=sh[0], s1=sh[1], s2=sh[2];
        scur[idx*3+0]=s0; scur[idx*3+1]=s1; scur[idx*3+2]=s2;
        out[idx*3+0] = s0 + pr_b1[0];
        out[idx*3+1] = s1 + pr_b1[1];
        out[idx*3+2] = s2 + pr_b1[2];
        float* pp = pein + (size_t)idx*16;
#pragma unroll
        for (int h=0; h<NH_; ++h) {
            const float* sd = s_delta + ((size_t)(b*NH_+h)*N_ + n)*3;
            pp[h*3+0]=sd[0]; pp[h*3+1]=sd[1]; pp[h*3+2]=sd[2];
            pp[12+h] = a_hist[(b*NH_+h)*N_ + n];
        }
    } else {
        // wcvt: fp32 -> fp16, k2-interleaved: dst[(k>>1)*512 + c*2 + (k&1)]
        int i = (bid - COMBO_TOPK - COMBO_PREP)*256 + tid;
        const float* src; __half* dst;
        int idx = i;
        if (idx < 256*NF_)        { src = pe_w1;  dst = H + HW_PE1; }
        else if (idx < 512*NF_)   { src = re_w1;  dst = H + HW_RE1; idx -= 256*NF_; }
        else if (idx < 768*NF_)   { src = re_w2;  dst = H + HW_RE2; idx -= 512*NF_; }
        else if (idx < 1536*NF_)  { src = rp_w;   dst = H + HW_RP;  idx -= 768*NF_; }
        else if (idx < 2048*NF_)  { src = pp_w;   dst = H + HW_PP;  idx -= 1536*NF_; }
        else                      { src = pr_w0;  dst = H + HW_PR0; idx -= 2048*NF_; }
        int k = idx >> 8, c = idx & 255;
        dst[(k>>1)*512 + c*2 + (k&1)] = __float2half_rn(src[idx]);
    }
}

// ---------------------------------------------------------------------------
__global__ void __launch_bounds__(1024)
scan_kernel(const float* __restrict__ flag, int* __restrict__ offsets,
            int* __restrict__ Mact)
{
    __shared__ int wsum[32];
    int tid = threadIdx.x;
    int lane = tid & 31, wrp = tid >> 5;

    float v[40];
    if (tid < 1000) {
        const float4* f4 = (const float4*)(flag + tid*40);
#pragma unroll
        for (int i=0;i<10;++i) {
            float4 t = f4[i];
            v[i*4+0]=t.x; v[i*4+1]=t.y; v[i*4+2]=t.z; v[i*4+3]=t.w;
        }
    } else {
#pragma unroll
        for (int i=0;i<40;++i) v[i]=0.f;
    }
    int local[4];
    int run = 0;
#pragma unroll
    for (int q=0;q<4;++q) {
        int c = 0;
#pragma unroll
        for (int k=0;k<K_TOP;++k) c += (v[q*10+k] != 0.f);
        local[q]=run; run += c;
    }
    int inc = run;
#pragma unroll
    for (int d=1; d<32; d<<=1) {
        int t = __shfl_up_sync(0xffffffffu, inc, d);
        if (lane >= d) inc += t;
    }
    if (lane == 31) wsum[wrp] = inc;
    __syncthreads();
    if (wrp == 0) {
        int w = wsum[lane];
#pragma unroll
        for (int d=1; d<32; d<<=1) {
            int t = __shfl_up_sync(0xffffffffu, w, d);
            if (lane >= d) w += t;
        }
        wsum[lane] = w;
    }
    __syncthreads();
    int before = inc - run + (wrp ? wsum[wrp-1] : 0);
#pragma unroll
    for (int q=0;q<4;++q) {
        int node = tid*4+q;
        if (node < NODES) offsets[node] = before + local[q];
    }
    if (tid == 1023) { int tot = wsum[31]; offsets[NODES] = tot; Mact[0] = tot; }
}

// ---------------------------------------------------------------------------
__global__ void fill_kernel(const float* __restrict__ scur, const float* __restrict__ acur,
                            const int* __restrict__ send, const float* __restrict__ flag,
                            const int* __restrict__ offsets,
                            int* __restrict__ sendc, float* __restrict__ rein)
{
    int r = blockIdx.x*blockDim.x+threadIdx.x;
    if (r >= EDGES) return;
    if (flag[r] == 0.f) return;
    int node = r / K_TOP, k = r % K_TOP;
    int rank = 0;
    for (int kk = 0; kk < k; ++kk) rank += (flag[node*K_TOP+kk] != 0.f);
    int pos = offsets[node] + rank;
    int s = send[r];
    sendc[pos] = s;
    float* o = rein + (size_t)pos*5;
    o[0] = acur[node];
    o[1] = acur[s];
    o[2] = scur[node*3+0] - scur[s*3+0];
    o[3] = scur[node*3+1] - scur[s*3+1];
    o[4] = scur[node*3+2] - scur[s*3+2];
}

// ---------------------------------------------------------------------------
// direct small-K GEMM: 32 rows/block, fp16 output
// ---------------------------------------------------------------------------
struct GDesc {
    const float* A; const float* W; const float* bias; __half* C;
    const int* Mp; int Mconst; int K; int ntiles;
};

__global__ void __launch_bounds__(256)
smallk_multi(GDesc d0, GDesc d1)
{
    int bx = blockIdx.x;
    GDesc d;
    if (bx < d0.ntiles) d = d0;
    else { bx -= d0.ntiles; d = d1; }

    int M = d.Mp ? __ldg(d.Mp) : d.Mconst;
    int bm = bx * 32;
    if (bm >= M) return;
    int K = d.K;

    __shared__ float Ws[16][NF_];
    __shared__ float Asm[32][17];
    int tid = threadIdx.x;

    for (int i = tid; i < K*NF_; i += 256) Ws[i>>8][i&255] = d.W[i];
    int rows = M - bm; if (rows > 32) rows = 32;
    for (int i = tid; i < rows*K; i += 256) {
        int r = i / K, k = i % K;
        Asm[r][k] = d.A[(size_t)(bm+r)*K + k];
    }
    __syncthreads();

    float b = d.bias[tid];
    if (K == 16) {
        for (int r = 0; r < rows; ++r) {
            float acc = b;
#pragma unroll
            for (int k = 0; k < 16; ++k) acc = fmaf(Asm[r][k], Ws[k][tid], acc);
            d.C[(size_t)(bm+r)*NF_ + tid] = __float2half_rn(fmaxf(acc, 0.f));
        }
    } else {  // K == 5
        for (int r = 0; r < rows; ++r) {
            float acc = b;
#pragma unroll
            for (int k = 0; k < 5; ++k) acc = fmaf(Asm[r][k], Ws[k][tid], acc);
            d.C[(size_t)(bm+r)*NF_ + tid] = __float2half_rn(fmaxf(acc, 0.f));
        }
    }
}

// ---------------------------------------------------------------------------
struct TDesc {
    const __half* A; const __half* W; const float* bias;
    const float* add0; const __half* add1; void* C;
    const int* Mp; int Mconst; int relu; int out_mode; int rt;
    const float* w1; float* outp; int ntiles;
};

#define SA2 40    // A smem stride (halves)
#define SB2 272   // B smem stride (halves)

// ---------------------------------------------------------------------------
// fp16 tc GEMM, 128x128 tiles, m16n8k16, software-pipelined
// ---------------------------------------------------------------------------
__global__ void __launch_bounds__(256, 2)
tc_multi(TDesc d0, TDesc d1, TDesc d2, TDesc d3)
{
    int bx = blockIdx.x;
    TDesc d;
    if (bx < d0.ntiles) d = d0;
    else { bx -= d0.ntiles;
        if (bx < d1.ntiles) d = d1;
        else { bx -= d1.ntiles;
            if (bx < d2.ntiles) d = d2;
            else { bx -= d2.ntiles; d = d3; } } }

    int M = d.Mp ? __ldg(d.Mp) : d.Mconst;
    int bm = (bx >> 1) * 128;
    if (bm >= M) return;
    int bn = (bx & 1) * 128;
    const __half* A = d.A;
    const __half* W = d.W;

    __shared__ __align__(16) __half As[2][128*SA2];
    __shared__ __align__(16) __half Bs[2][8*SB2];

    int tid = threadIdx.x;
    int wid = tid >> 5, lane = tid & 31;
    int gid = lane >> 2, tig = lane & 3;
    int warp_m = (wid & 3) * 32;
    int warp_n = (wid >> 2) * 64;

    int a_row = tid >> 1, a_kq = (tid & 1) * 8;
    int b_k2 = tid >> 5,  b_c8 = (tid & 31) * 8;

    uint4 ar, br;

#define TCP_LDG(k0)                                                           \
    {                                                                         \
        int gm = bm + a_row;                                                  \
        ar = make_uint4(0,0,0,0);                                             \
        if (gm < M) ar = *(const uint4*)(A + (size_t)gm * NF_ + (k0) + a_kq); \
        br = *(const uint4*)(W + (size_t)(((k0)>>1) + b_k2) * 512 + bn*2 + b_c8);\
    }

#define TCP_STS(buf)                                                          \
    {                                                                         \
        *(uint4*)&As[buf][a_row*SA2 + a_kq] = ar;                             \
        *(uint4*)&Bs[buf][b_k2*SB2 + b_c8] = br;                              \
    }

    float acc[2][8][4];
#pragma unroll
    for (int f=0;f<2;++f)
#pragma unroll
        for (int g=0;g<8;++g)
#pragma unroll
            for (int q=0;q<4;++q) acc[f][g][q]=0.f;

    TCP_LDG(0);
    TCP_STS(0);
    __syncthreads();

#pragma unroll 1
    for (int t = 0; t < 16; ++t) {
        int cur = t & 1, nxt = cur ^ 1;
        if (t + 1 < 16) TCP_LDG((t + 1) * 16);
        {
            unsigned a[2][4], bfr[8][2];
#pragma unroll
            for (int f = 0; f < 2; ++f) {
                int r0 = warp_m + f*16 + gid;
                a[f][0] = *(const unsigned*)&As[cur][r0*SA2 + 2*tig];
                a[f][1] = *(const unsigned*)&As[cur][(r0+8)*SA2 + 2*tig];
                a[f][2] = *(const unsigned*)&As[cur][r0*SA2 + 2*tig + 8];
                a[f][3] = *(const unsigned*)&As[cur][(r0+8)*SA2 + 2*tig + 8];
            }
#pragma unroll
            for (int g = 0; g < 8; ++g) {
                int col = warp_n + g*8 + gid;
                bfr[g][0] = *(const unsigned*)&Bs[cur][tig*SB2 + col*2];
                bfr[g][1] = *(const unsigned*)&Bs[cur][(tig+4)*SB2 + col*2];
            }
#pragma unroll
            for (int f = 0; f < 2; ++f)
#pragma unroll
                for (int g = 0; g < 8; ++g) {
                    asm volatile(
                        "mma.sync.aligned.m16n8k16.row.col.f32.f16.f16.f32 "
                        "{%0,%1,%2,%3},{%4,%5,%6,%7},{%8,%9},{%0,%1,%2,%3};"
                        : "+f"(acc[f][g][0]), "+f"(acc[f][g][1]),
                          "+f"(acc[f][g][2]), "+f"(acc[f][g][3])
                        : "r"(a[f][0]), "r"(a[f][1]), "r"(a[f][2]), "r"(a[f][3]),
                          "r"(bfr[g][0]), "r"(bfr[g][1]));
                }
        }
        if (t + 1 < 16) TCP_STS(nxt);
        __syncthreads();
    }
#undef TCP_LDG
#undef TCP_STS

#pragma unroll
    for (int f = 0; f < 2; ++f) {
        int r0 = bm + warp_m + f*16 + gid;
        int r1 = r0 + 8;
#pragma unroll
        for (int g = 0; g < 8; ++g) {
            int ccol = bn + warp_n + g*8 + tig*2;
            float b0 = d.bias ? d.bias[ccol] : 0.f;
            float b1 = d.bias ? d.bias[ccol+1] : 0.f;
#pragma unroll
            for (int h = 0; h < 2; ++h) {
                int r = h ? r1 : r0;
                if (r >= M) continue;
                size_t off = (size_t)r * NF_ + ccol;
                float v0 = acc[f][g][2*h+0] + b0;
                float v1 = acc[f][g][2*h+1] + b1;
                if (d.add0) { v0 += d.add0[off]; v1 += d.add0[off+1]; }
                if (d.add1) { v0 += __half2float(d.add1[off]); v1 += __half2float(d.add1[off+1]); }
                if (d.relu) { v0 = fmaxf(v0,0.f); v1 = fmaxf(v1,0.f); }
                if (d.rt)   { *(__half2*)((__half*)d.C + off) = __floats2half2_rn(v0, v1); }
                else        { *(float2*)((float*)d.C + off) = make_float2(v0, v1); }
            }
        }
    }
}

// ---------------------------------------------------------------------------
// fp16 tc GEMM, 64x128 tiles, m16n8k16, software-pipelined
// ---------------------------------------------------------------------------
__global__ void __launch_bounds__(256, 2)
tc64_multi(TDesc d0, TDesc d1)
{
    int bx = blockIdx.x;
    TDesc d;
    if (bx < d0.ntiles) d = d0;
    else { bx -= d0.ntiles; d = d1; }

    int M = d.Mconst;
    int bm = (bx >> 1) * 64;
    if (bm >= M) return;
    int bn = (bx & 1) * 128;
    const __half* A = d.A;
    const __half* W = d.W;

    __shared__ __align__(16) __half As[2][64*SA2];
    __shared__ __align__(16) __half Bs[2][8*SB2];

    int tid = threadIdx.x;
    int wid = tid >> 5, lane = tid & 31;
    int gid = lane >> 2, tig = lane & 3;
    int warp_m = (wid & 1) * 32;
    int warp_n = (wid >> 1) * 32;

    int a_row = tid >> 2, a_kq = (tid & 3) * 4;
    int b_k2 = tid >> 5,  b_c8 = (tid & 31) * 8;

    uint2 ar; uint4 br;

#define TCP64_LDG(k0)                                                         \
    {                                                                         \
        int gm = bm + a_row;                                                  \
        ar = make_uint2(0,0);                                                 \
        if (gm < M) ar = *(const uint2*)(A + (size_t)gm * NF_ + (k0) + a_kq); \
        br = *(const uint4*)(W + (size_t)(((k0)>>1) + b_k2) * 512 + bn*2 + b_c8);\
    }

#define TCP64_STS(buf)                                                        \
    {                                                                         \
        *(uint2*)&As[buf][a_row*SA2 + a_kq] = ar;                             \
        *(uint4*)&Bs[buf][b_k2*SB2 + b_c8] = br;                              \
    }

    float acc[2][4][4];
#pragma unroll
    for (int f=0;f<2;++f)
#pragma unroll
        for (int g=0;g<4;++g)
#pragma unroll
            for (int q=0;q<4;++q) acc[f][g][q]=0.f;

    TCP64_LDG(0);
    TCP64_STS(0);
    __syncthreads();

#pragma unroll 1
    for (int t = 0; t < 16; ++t) {
        int cur = t & 1, nxt = cur ^ 1;
        if (t + 1 < 16) TCP64_LDG((t + 1) * 16);
        {
            unsigned a[2][4], bfr[4][2];
#pragma unroll
            for (int f = 0; f < 2; ++f) {
                int r0 = warp_m + f*16 + gid;
                a[f][0] = *(const unsigned*)&As[cur][r0*SA2 + 2*tig];
                a[f][1] = *(const unsigned*)&As[cur][(r0+8)*SA2 + 2*tig];
                a[f][2] = *(const unsigned*)&As[cur][r0*SA2 + 2*tig + 8];
                a[f][3] = *(const unsigned*)&As[cur][(r0+8)*SA2 + 2*tig + 8];
            }
#pragma unroll
            for (int g = 0; g < 4; ++g) {
                int col = warp_n + g*8 + gid;
                bfr[g][0] = *(const unsigned*)&Bs[cur][tig*SB2 + col*2];
                bfr[g][1] = *(const unsigned*)&Bs[cur][(tig+4)*SB2 + col*2];
            }
#pragma unroll
            for (int f = 0; f < 2; ++f)
#pragma unroll
                for (int g = 0; g < 4; ++g) {
                    asm volatile(
                        "mma.sync.aligned.m16n8k16.row.col.f32.f16.f16.f32 "
                        "{%0,%1,%2,%3},{%4,%5,%6,%7},{%8,%9},{%0,%1,%2,%3};"
                        : "+f"(acc[f][g][0]), "+f"(acc[f][g][1]),
                          "+f"(acc[f][g][2]), "+f"(acc[f][g][3])
                        : "r"(a[f][0]), "r"(a[f][1]), "r"(a[f][2]), "r"(a[f][3]),
                          "r"(bfr[g][0]), "r"(bfr[g][1]));
                }
        }
        if (t + 1 < 16) TCP64_STS(nxt);
        __syncthreads();
    }
#undef TCP64_LDG
#undef TCP64_STS

    if (!d.out_mode) {
#pragma unroll
        for (int f = 0; f < 2; ++f) {
            int r0 = bm + warp_m + f*16 + gid;
            int r1 = r0 + 8;
#pragma unroll
            for (int g = 0; g < 4; ++g) {
                int ccol = bn + warp_n + g*8 + tig*2;
                float b0 = d.bias ? d.bias[ccol] : 0.f;
                float b1 = d.bias ? d.bias[ccol+1] : 0.f;
#pragma unroll
                for (int h = 0; h < 2; ++h) {
                    int r = h ? r1 : r0;
                    if (r >= M) continue;
                    size_t off = (size_t)r * NF_ + ccol;
                    float v0 = acc[f][g][2*h+0] + b0;
                    float v1 = acc[f][g][2*h+1] + b1;
                    if (d.add0) { v0 += d.add0[off]; v1 += d.add0[off+1]; }
                    if (d.add1) { v0 += __half2float(d.add1[off]); v1 += __half2float(d.add1[off+1]); }
                    if (d.relu) { v0 = fmaxf(v0,0.f); v1 = fmaxf(v1,0.f); }
                    if (d.rt)   { *(__half2*)((__half*)d.C + off) = __floats2half2_rn(v0, v1); }
                    else        { *(float2*)((float*)d.C + off) = make_float2(v0, v1); }
                }
            }
        }
    } else {
        // hout = relu(acc + bias); out[row] += hout-slice @ w1 (256x3)
#pragma unroll
        for (int f = 0; f < 2; ++f) {
            int r0 = bm + warp_m + f*16 + gid;
            int r1 = r0 + 8;
            float p0[3] = {0.f,0.f,0.f};
            float p1[3] = {0.f,0.f,0.f};
#pragma unroll
            for (int g = 0; g < 4; ++g) {
                int ccol = bn + warp_n + g*8 + tig*2;
#pragma unroll
                for (int c = 0; c < 2; ++c) {
                    int col = ccol + c;
                    float w0 = __ldg(d.w1 + col*3 + 0);
                    float wv = __ldg(d.w1 + col*3 + 1);
                    float w2 = __ldg(d.w1 + col*3 + 2);
                    float bb = d.bias[col];
                    float v0 = fmaxf(acc[f][g][0+c] + bb, 0.f);
                    float v1 = fmaxf(acc[f][g][2+c] + bb, 0.f);
                    p0[0]=fmaf(v0,w0,p0[0]); p0[1]=fmaf(v0,wv,p0[1]); p0[2]=fmaf(v0,w2,p0[2]);
                    p1[0]=fmaf(v1,w0,p1[0]); p1[1]=fmaf(v1,wv,p1[1]); p1[2]=fmaf(v1,w2,p1[2]);
                }
            }
#pragma unroll
            for (int j = 0; j < 3; ++j) {
                p0[j] += __shfl_xor_sync(0xffffffffu, p0[j], 1);
                p0[j] += __shfl_xor_sync(0xffffffffu, p0[j], 2);
                p1[j] += __shfl_xor_sync(0xffffffffu, p1[j], 1);
                p1[j] += __shfl_xor_sync(0xffffffffu, p1[j], 2);
            }
            if (tig == 0) {
                if (r0 < M) {
                    atomicAdd(d.outp + r0*3 + 0, p0[0]);
                    atomicAdd(d.outp + r0*3 + 1, p0[1]);
                    atomicAdd(d.outp + r0*3 + 2, p0[2]);
                }
                if (r1 < M) {
                    atomicAdd(d.outp + r1*3 + 0, p1[0]);
                    atomicAdd(d.outp + r1*3 + 1, p1[1]);
                    atomicAdd(d.outp + r1*3 + 2, p1[2]);
                }
            }
        }
    }
}

// ---------------------------------------------------------------------------
// agg: fp16 inputs (base/G2/G3), fp32 accumulate, fp16 output
// ---------------------------------------------------------------------------
__global__ void agg_kernel(const __half* __restrict__ base, const __half* __restrict__ G2,
                           const __half* __restrict__ G3,
                           const int* __restrict__ sendc, const int* __restrict__ offsets,
                           __half* __restrict__ agg)
{
    int w = blockIdx.x*blockDim.x + threadIdx.x;
    if (w >= NODES*64) return;
    int node = w >> 6, q = (w & 63) * 4;
    __half2 g2h0 = *(const __half2*)(G2 + (size_t)node*NF_ + q);
    __half2 g2h1 = *(const __half2*)(G2 + (size_t)node*NF_ + q + 2);
    float2 g2a = __half22float2(g2h0), g2b = __half22float2(g2h1);
    int e0 = offsets[node], e1 = offsets[node+1];
    float4 a = make_float4(0.f,0.f,0.f,0.f);
    for (int e = e0; e < e1; ++e) {
        uint2 bsu = *(const uint2*)(base + (size_t)e*NF_ + q);
        uint2 g3u = *(const uint2*)(G3 + (size_t)sendc[e]*NF_ + q);
        float2 bs0 = __half22float2(*(__half2*)&bsu.x);
        float2 bs1 = __half22float2(*(__half2*)&bsu.y);
        float2 g30 = __half22float2(*(__half2*)&g3u.x);
        float2 g31 = __half22float2(*(__half2*)&g3u.y);
        a.x += fmaxf(bs0.x + g2a.x + g30.x, 0.f);
        a.y += fmaxf(bs0.y + g2a.y + g30.y, 0.f);
        a.z += fmaxf(bs1.x + g2b.x + g31.x, 0.f);
        a.w += fmaxf(bs1.y + g2b.y + g31.y, 0.f);
    }
    __half2 h0 = __floats2half2_rn(a.x, a.y);
    __half2 h1 = __floats2half2_rn(a.z, a.w);
    *(__half2*)(agg + (size_t)node*NF_ + q)     = h0;
    *(__half2*)(agg + (size_t)node*NF_ + q + 2) = h1;
}

// ---------------------------------------------------------------------------
extern "C" void kernel_launch(void* const* d_in, const int* in_sizes, int n_in,
                              void* d_out, int out_size)
{
    const float* a_hist =(const float*)d_in[0];
    const float* s_hist =(const float*)d_in[1];
    const float* s_delta=(const float*)d_in[2];
    const float* pe_w0=(const float*)d_in[3];  const float* pe_b0=(const float*)d_in[4];
    const float* pe_w1=(const float*)d_in[5];  const float* pe_b1=(const float*)d_in[6];
    const float* re_w0=(const float*)d_in[7];  const float* re_b0=(const float*)d_in[8];
    const float* re_w1=(const float*)d_in[9];  const float* re_b1=(const float*)d_in[10];
    const float* re_w2=(const float*)d_in[11]; const float* re_b2=(const float*)d_in[12];
    const float* rp_w =(const float*)d_in[13]; const float* rp_b =(const float*)d_in[14];
    const float* pp_w =(const float*)d_in[15]; const float* pp_b =(const float*)d_in[16];
    const float* pr_w0=(const float*)d_in[17]; const float* pr_b0=(const float*)d_in[18];
    const float* pr_w1=(const float*)d_in[19]; const float* pr_b1=(const float*)d_in[20];
    float* out = (float*)d_out;

    void* sp;   cudaGetSymbolAddress(&sp, g_scratch);
    void* hp;   cudaGetSymbolAddress(&hp, g_half);
    void* p1;   cudaGetSymbolAddress(&p1, g_send);
    void* p2;   cudaGetSymbolAddress(&p2, g_sendc);
    void* p3;   cudaGetSymbolAddress(&p3, g_offsets);
    void* p4;   cudaGetSymbolAddress(&p4, g_Mact);
    float*  S = (float*)sp;
    __half* H = (__half*)hp;
    int* send    = (int*)p1;
    int* sendc   = (int*)p2;
    int* offsets = (int*)p3;
    int* Mact    = (int*)p4;

    float* scur=S+OFF_SCUR; float* acur=S+OFF_ACUR; float* pein=S+OFF_PEIN;
    float* flag=S+OFF_FLAG; float* rein=S+OFF_REIN; float* ppc =S+OFF_PPC;
    __half* peh =H+HOFF_PEH;  __half* pe  =H+HOFF_PE;   __half* agg =H+HOFF_AGG;
    __half* G2  =H+HOFF_G2;   __half* G3  =H+HOFF_G3;
    __half* bufA=H+HOFF_BUFA; __half* bufB=H+HOFF_BUFB; __half* base=H+HOFF_BASE;
    __half* wPE1=H+HW_PE1; __half* wRE1=H+HW_RE1; __half* wRE2=H+HW_RE2;
    __half* wRP =H+HW_RP;  __half* wPP =H+HW_PP;  __half* wPR0=H+HW_PR0;

    const int NT_NODE   = ((NODES+127)/128)*2;  // 64
    const int NT_NODE64 = ((NODES+63)/64)*2;    // 126
    const int NT_EDGE   = ((EDGES+127)/128)*2;  // 626 worst case

    TDesc Z = {};

    auto TD = [&](const __half* A,const __half* W,const float* bias,
                  const float* a0,const __half* a1,void* C,
                  const int* Mp,int Mc,int relu,int rt,int nt)->TDesc {
        TDesc d; d.A=A; d.W=W; d.bias=bias; d.add0=a0; d.add1=a1; d.C=C;
        d.Mp=Mp; d.Mconst=Mc; d.relu=relu; d.out_mode=0; d.rt=rt;
        d.w1=0; d.outp=0; d.ntiles=nt;
        return d;
    };

    // combo: topk + prep + wcvt (all input-only)
    combo_kernel<<<COMBO_BLOCKS,256>>>(a_hist,s_hist,s_delta,pr_b1,
                                       pe_w1,re_w1,re_w2,rp_w,pp_w,pr_w0,
                                       S, H, send, flag, out);
    scan_kernel<<<1,1024>>>(flag, offsets, Mact);
    fill_kernel<<<(EDGES+255)/256,256>>>(scur,acur,send,flag,offsets,sendc,rein);

    // L1: peh (K=16, node) + bufA (K=5, edges) — 32 rows/block, fp16 out
    {
        GDesc dA; dA.A=pein; dA.W=pe_w0; dA.bias=pe_b0; dA.C=peh;
        dA.Mp=0; dA.Mconst=NODES; dA.K=16; dA.ntiles=(NODES+31)/32;
        GDesc dB; dB.A=rein; dB.W=re_w0; dB.bias=re_b0; dB.C=bufA;
        dB.Mp=Mact; dB.Mconst=0; dB.K=5; dB.ntiles=(EDGES+31)/32;
        smallk_multi<<<dA.ntiles+dB.ntiles,256>>>(dA,dB);
    }
    // L2: pe = relu(peh@wPE1+b) [h]  +  bufB = relu(bufA@wRE1+b) [h]
    {
        TDesc a = TD(peh, wPE1, pe_b1, 0,0, pe,  0, NODES, 1, 1, NT_NODE);
        TDesc b = TD(bufA, wRE1, re_b1, 0,0, bufB, Mact, 0, 1, 1, NT_EDGE);
        tc_multi<<<a.ntiles+b.ntiles,256>>>(a,b,Z,Z);
    }
    // L3: ppc (f32) + renc [h] + G2_0 + G3_0 (h)
    {
        TDesc a = TD(pe,   wPP,  pp_b,  0,0, ppc,  0, NODES, 0, 0, NT_NODE);
        TDesc b = TD(bufB, wRE2, re_b2, 0,0, bufA, Mact, 0, 1, 1, NT_EDGE);
        TDesc c = TD(pe, wRP + 256*NF_, 0, 0,0, G2, 0, NODES, 0, 1, NT_NODE);
        TDesc d = TD(pe, wRP + 512*NF_, 0, 0,0, G3, 0, NODES, 0, 1, NT_NODE);
        tc_multi<<<a.ntiles+b.ntiles+c.ntiles+d.ntiles,256>>>(a,b,c,d);
    }
    // L4: base = renc @ wRP[0:256] + rp_b  (h)
    {
        TDesc a = TD(bufA, wRP, rp_b, 0,0, base, Mact, 0, 0, 1, NT_EDGE);
        tc_multi<<<a.ntiles,256>>>(a,Z,Z,Z);
    }

    for (int step=0; step<3; ++step) {
        agg_kernel<<<(NODES*64+255)/256,256>>>(base, G2, G3, sendc, offsets, agg);
        // J: pe = relu(ppc + agg@wPP[256:] + pe) [h]
        TDesc j = TD(agg, wPP + 256*NF_, 0, ppc, pe, pe, 0, NODES, 1, 1, NT_NODE64);
        tc64_multi<<<j.ntiles,256>>>(j,Z);
        if (step < 2) {
            TDesc c = TD(pe, wRP + 256*NF_, 0, 0,0, G2, 0, NODES, 0, 1, NT_NODE64);
            TDesc d = TD(pe, wRP + 512*NF_, 0, 0,0, G3, 0, NODES, 0, 1, NT_NODE64);
            tc64_multi<<<c.ntiles+d.ntiles,256>>>(c,d);
        }
    }

    // final: pr GEMM with fused 256->3 output epilogue
    {
        TDesc k = TD(pe, wPR0, pr_b0, 0,0, 0, 0, NODES, 1, 0, NT_NODE64);
        k.out_mode = 1; k.w1 = pr_w1; k.outp = out;
        tc64_multi<<<k.ntiles,256>>>(k,Z);
    }
}